// round 12
// baseline (speedup 1.0000x reference)
#include <cuda_runtime.h>
#include <cstdint>

#define BATCH 8
#define NPTS  32768
#define NG    256
#define NC    64
#define ACAP  2048   // per-anchor capacity in k4 (trigger >1024, chunk adds <=1024: overflow-proof)

__device__ float4 g_pbb[BATCH * NPTS];     // x,y,z,|p|^2 (square-then-add)
__device__ int    g_fps[BATCH * NG];
__device__ float  g_code[BATCH * 256];
__device__ float  g_cdot[BATCH * 256];
__device__ float  g_rec[BATCH * NG * 3];
__device__ int    g_knn[BATCH * NG * NC];

// ---------------- K0: SoA prep + zero code ----------------
__global__ void k0_prep(const float* __restrict__ pts) {
    int i = blockIdx.x * 256 + threadIdx.x;
    float x = pts[i * 3], y = pts[i * 3 + 1], z = pts[i * 3 + 2];
    float bb = __fadd_rn(__fadd_rn(__fmul_rn(x, x), __fmul_rn(y, y)), __fmul_rn(z, z));
    g_pbb[i] = make_float4(x, y, z, bb);
    if (i < BATCH * 256) g_code[i] = 0.0f;
}

// ---------------- K1: FPS — 8-CTA cluster per batch ----------------
// R9's xyz-carrying DSMEM exchange (winner never re-fetched from L2) combined
// with R10's mbarrier sync (no ~490-cyc barrier.cluster per iteration).
// Exchange double-buffered by iteration parity; the trailing __syncthreads
// orders every thread's parity-p reads before this CTA's leader can produce
// the it+2 write targeting parity p (leader must pass phase it+1 first).
__global__ void __cluster_dims__(8, 1, 1) __launch_bounds__(512, 1) k1_fps() {
    __shared__ float s_wv[16];
    __shared__ int   s_wi[16];
    __shared__ float s_wx[16], s_wy[16], s_wz[16];
    __shared__ __align__(16) unsigned int s_exch[2][8 * 8];   // [parity][cta*8 words], 32B records
    __shared__ __align__(8) unsigned long long s_mb;

    int rank = blockIdx.x & 7;
    int b    = blockIdx.x >> 3;
    int tid  = threadIdx.x;
    int base = rank * 4096;

    const float4* __restrict__ pb = g_pbb + b * NPTS;

    float px[8], py[8], pz[8], dist[8];
#pragma unroll
    for (int j = 0; j < 8; j++) {
        float4 q = pb[base + tid + j * 512];
        px[j] = q.x; py[j] = q.y; pz[j] = q.z; dist[j] = 1e10f;
    }
    float4 q0 = pb[0];
    float sx = q0.x, sy = q0.y, sz = q0.z;
    int cur = 0;

    unsigned int mb  = (unsigned int)__cvta_generic_to_shared(&s_mb);
    unsigned int ex0 = (unsigned int)__cvta_generic_to_shared(&s_exch[0][0]);
    unsigned int ex1 = (unsigned int)__cvta_generic_to_shared(&s_exch[1][0]);

    if (tid == 0)
        asm volatile("mbarrier.init.shared.b64 [%0], 8;" :: "r"(mb) : "memory");
    asm volatile("barrier.cluster.arrive.aligned;" ::: "memory");
    asm volatile("barrier.cluster.wait.aligned;" ::: "memory");

    for (int it = 0; it < NG; it++) {
        if (rank == 0 && tid == 0) g_fps[b * NG + it] = cur;

        float bv = -1.0f, bx = 0.f, by = 0.f, bz = 0.f;
        int bi = 0x7fffffff;
#pragma unroll
        for (int j = 0; j < 8; j++) {
            float dx = __fsub_rn(px[j], sx), dy = __fsub_rn(py[j], sy), dz = __fsub_rn(pz[j], sz);
            float dd = __fadd_rn(__fadd_rn(__fmul_rn(dx, dx), __fmul_rn(dy, dy)), __fmul_rn(dz, dz));
            float nd = fminf(dist[j], dd);
            dist[j] = nd;
            if (nd > bv) { bv = nd; bi = base + tid + j * 512; bx = px[j]; by = py[j]; bz = pz[j]; }
        }
#pragma unroll
        for (int off = 16; off; off >>= 1) {
            float ov = __shfl_down_sync(~0u, bv, off);
            int   oi = __shfl_down_sync(~0u, bi, off);
            float ox = __shfl_down_sync(~0u, bx, off);
            float oy = __shfl_down_sync(~0u, by, off);
            float oz = __shfl_down_sync(~0u, bz, off);
            if (ov > bv || (ov == bv && oi < bi)) { bv = ov; bi = oi; bx = ox; by = oy; bz = oz; }
        }
        if ((tid & 31) == 0) {
            int w = tid >> 5;
            s_wv[w] = bv; s_wi[w] = bi; s_wx[w] = bx; s_wy[w] = by; s_wz[w] = bz;
        }
        __syncthreads();
        if (tid < 32) {
            bool ok = tid < 16;
            bv = ok ? s_wv[tid] : -1.0f;
            bi = ok ? s_wi[tid] : 0x7fffffff;
            bx = ok ? s_wx[tid] : 0.f;
            by = ok ? s_wy[tid] : 0.f;
            bz = ok ? s_wz[tid] : 0.f;
#pragma unroll
            for (int off = 8; off; off >>= 1) {
                float ov = __shfl_down_sync(~0u, bv, off);
                int   oi = __shfl_down_sync(~0u, bi, off);
                float ox = __shfl_down_sync(~0u, bx, off);
                float oy = __shfl_down_sync(~0u, by, off);
                float oz = __shfl_down_sync(~0u, bz, off);
                if (ov > bv || (ov == bv && oi < bi)) { bv = ov; bi = oi; bx = ox; by = oy; bz = oz; }
            }
            // broadcast CTA winner record to lanes 0..7
            bv = __shfl_sync(~0u, bv, 0);
            bi = __shfl_sync(~0u, bi, 0);
            bx = __shfl_sync(~0u, bx, 0);
            by = __shfl_sync(~0u, by, 0);
            bz = __shfl_sync(~0u, bz, 0);
            if (tid < 8) {
                unsigned int exb = (it & 1) ? ex1 : ex0;
                unsigned int v0 = __float_as_uint(bv);
                unsigned int v1 = (unsigned int)bi;
                unsigned int v2 = __float_as_uint(bx);
                unsigned int v3 = __float_as_uint(by);
                unsigned int v4 = __float_as_uint(bz);
                unsigned int ra, rb;
                asm volatile("mapa.shared::cluster.u32 %0, %1, %2;"
                             : "=r"(ra) : "r"(exb + rank * 32), "r"(tid));
                asm volatile("st.shared::cluster.v4.b32 [%0], {%1,%2,%3,%4};"
                             :: "r"(ra), "r"(v0), "r"(v1), "r"(v2), "r"(v3) : "memory");
                asm volatile("st.shared::cluster.b32 [%0+16], %1;"
                             :: "r"(ra), "r"(v4) : "memory");
                asm volatile("mapa.shared::cluster.u32 %0, %1, %2;"
                             : "=r"(rb) : "r"(mb), "r"(tid));
                asm volatile("mbarrier.arrive.release.cluster.shared::cluster.b64 _, [%0];"
                             :: "r"(rb) : "memory");
            }
        }
        {
            unsigned int parity = (unsigned int)(it & 1);
            asm volatile(
                "{\n\t.reg .pred P;\n\t"
                "WL%=:\n\t"
                "mbarrier.try_wait.parity.acquire.cluster.shared::cta.b64 P, [%0], %1, 0x989680;\n\t"
                "@!P bra WL%=;\n\t}"
                :: "r"(mb), "r"(parity) : "memory");
        }
        const unsigned int* e = s_exch[it & 1];
        float wv = -1.0f; int wi = 0x7fffffff;
        float nsx = sx, nsy = sy, nsz = sz;
#pragma unroll
        for (int r = 0; r < 8; r++) {
            float v = __uint_as_float(e[r * 8 + 0]);
            int   i = (int)e[r * 8 + 1];
            if (v > wv || (v == wv && i < wi)) {
                wv = v; wi = i;
                nsx = __uint_as_float(e[r * 8 + 2]);
                nsy = __uint_as_float(e[r * 8 + 3]);
                nsz = __uint_as_float(e[r * 8 + 4]);
            }
        }
        cur = wi; sx = nsx; sy = nsy; sz = nsz;
        __syncthreads();
    }
}

// ---------------- K2: g2sd encoder + maxpool ----------------
__global__ void __launch_bounds__(128) k2_genc(const float* __restrict__ w1, const float* __restrict__ b1,
                                               const float* __restrict__ w2, const float* __restrict__ b2) {
    __shared__ float h1[128];
    int bg = blockIdx.x, b = bg >> 8, j = threadIdx.x;
    int pi = g_fps[bg];
    float4 q = g_pbb[b * NPTS + pi];
    float a = __fmaf_rn(q.z, w1[256 + j], __fmaf_rn(q.y, w1[128 + j], __fmul_rn(q.x, w1[j])));
    h1[j] = fmaxf(__fadd_rn(a, b1[j]), 0.0f);
    __syncthreads();
#pragma unroll
    for (int t = 0; t < 2; t++) {
        int ch = j + t * 128;
        float s = 0.0f;
        for (int k = 0; k < 128; k++) s = __fmaf_rn(h1[k], w2[k * 256 + ch], s);
        float h2 = fmaxf(__fadd_rn(s, b2[ch]), 0.0f);
        atomicMax((int*)&g_code[b * 256 + ch], __float_as_int(h2));
    }
}

// ---------------- K3a: per-batch code @ gd_w1[2:,:] ----------------
__global__ void __launch_bounds__(256) k3a(const float* __restrict__ w1) {
    __shared__ float cs[256];
    int b = blockIdx.x, j = threadIdx.x;
    cs[j] = g_code[b * 256 + j];
    __syncthreads();
    float s = 0.0f;
    for (int k = 0; k < 256; k++) s = __fmaf_rn(cs[k], w1[(2 + k) * 256 + j], s);
    g_cdot[b * 256 + j] = s;
}

// ---------------- K3b: g2sd folding decoder -> rec_g ----------------
__global__ void __launch_bounds__(256) k3b(const float* __restrict__ w1, const float* __restrict__ b1,
                                           const float* __restrict__ w2, const float* __restrict__ b2) {
    __shared__ float h[256];
    int bg = blockIdx.x, b = bg >> 8, g = bg & 255, j = threadIdx.x;
    float gx = __fmul_rn((float)(g & 15) + 0.5f, 0.0625f);
    float gy = __fmul_rn((float)(g >> 4) + 0.5f, 0.0625f);
    float a = __fmaf_rn(gy, w1[256 + j], __fmul_rn(gx, w1[j]));
    a = __fadd_rn(a, g_cdot[b * 256 + j]);
    h[j] = fmaxf(__fadd_rn(a, b1[j]), 0.0f);
    __syncthreads();
    if (j < 3) {
        float s = 0.0f;
        for (int k = 0; k < 256; k++) s = __fmaf_rn(h[k], w2[k * 3 + j], s);
        g_rec[bg * 3 + j] = __fadd_rn(s, b2[j]);
    }
}

// ---------------- K4: exact 64-NN, 2 anchors per CTA share one point stream ----------------
__global__ void __launch_bounds__(256) k4_knn() {
    __shared__ unsigned long long buf[2][ACAP];   // 32 KB
    __shared__ int cnt[2];
    __shared__ unsigned long long thr_sh[2];
    __shared__ int s_flag;

    int bg2 = blockIdx.x;            // 0 .. BATCH*NG/2-1
    int b   = bg2 >> 7;              // 128 CTAs per batch
    int tid = threadIdx.x;

    float ax[2], ay[2], az[2], aa[2];
#pragma unroll
    for (int a = 0; a < 2; a++) {
        int bg = bg2 * 2 + a;
        ax[a] = g_rec[bg * 3]; ay[a] = g_rec[bg * 3 + 1]; az[a] = g_rec[bg * 3 + 2];
        aa[a] = __fadd_rn(__fadd_rn(__fmul_rn(ax[a], ax[a]), __fmul_rn(ay[a], ay[a])),
                          __fmul_rn(az[a], az[a]));
    }
    if (tid < 2) { cnt[tid] = 0; thr_sh[tid] = ~0ULL; }
    __syncthreads();

    unsigned long long thr[2] = {~0ULL, ~0ULL};
    const float4* __restrict__ pb = g_pbb + b * NPTS;

    auto compact1 = [&](int a) {
        int c = cnt[a];                    // uniform (post-sync)
        int S = 64; while (S < c) S <<= 1; // pow2 >= c (c <= ACAP)
        for (int t = tid; t < S; t += 256) if (t >= c) buf[a][t] = ~0ULL;
        __syncthreads();
        for (int k = 2; k <= S; k <<= 1)
            for (int j = k >> 1; j > 0; j >>= 1) {
                for (int t = tid; t < S; t += 256) {
                    int x = t ^ j;
                    if (x > t) {
                        unsigned long long A = buf[a][t], Bv = buf[a][x];
                        bool up = ((t & k) == 0);
                        if (up ? (A > Bv) : (A < Bv)) { buf[a][t] = Bv; buf[a][x] = A; }
                    }
                }
                __syncthreads();
            }
        if (tid == 0) { cnt[a] = NC; thr_sh[a] = buf[a][NC - 1]; }
        __syncthreads();
    };

    for (int base = 0; base < NPTS; base += 1024) {
#pragma unroll
        for (int i = 0; i < 4; i++) {
            int p = base + tid + i * 256;
            float4 q = pb[p];
#pragma unroll
            for (int a = 0; a < 2; a++) {
                float ab = __fmaf_rn(az[a], q.z, __fmaf_rn(ay[a], q.y, __fmul_rn(ax[a], q.x)));
                float dd = __fsub_rn(__fadd_rn(aa[a], q.w), __fmul_rn(2.0f, ab));
                unsigned int kb = __float_as_uint(dd);
                kb = (kb & 0x80000000u) ? ~kb : (kb | 0x80000000u);
                unsigned long long key = ((unsigned long long)kb << 32) | (unsigned int)p;
                if (key < thr[a]) {
                    int pos = atomicAdd(&cnt[a], 1);   // pos <= 2047 guaranteed
                    buf[a][pos] = key;
                }
            }
        }
        __syncthreads();
        if (tid == 0) {
            int f = 0;
            if (cnt[0] > 1024) f |= 1;
            if (cnt[1] > 1024) f |= 2;
            s_flag = f;
        }
        __syncthreads();
        int f = s_flag;
        if (f) {
            if (f & 1) compact1(0);
            if (f & 2) compact1(1);
            thr[0] = thr_sh[0]; thr[1] = thr_sh[1];
        }
    }
    if (cnt[0] > NC) compact1(0);
    if (cnt[1] > NC) compact1(1);
    // buf[a][0..63] sorted ascending by (d, idx)
    if (tid < 2 * NC) {
        int a = tid >> 6, t = tid & 63;
        g_knn[(bg2 * 2 + a) * NC + t] = (int)(unsigned int)(buf[a][t] & 0xffffffffu);
    }
}

// ---------------- K5: normalize + s2pf + rescale + resample + assemble ----------------
__global__ void __launch_bounds__(128) k5_patch(const float* __restrict__ sew1, const float* __restrict__ seb1,
                                                const float* __restrict__ sdw1, const float* __restrict__ sdb1,
                                                const float* __restrict__ sdw2, const float* __restrict__ sdb2,
                                                float* __restrict__ out) {
    __shared__ float px[NC], py[NC], pz[NC];
    __shared__ float nx[NC], ny[NC], nz[NC], nrm[NC];
    __shared__ float code[128];
    __shared__ float h2s[NC * 129];
    __shared__ float cen[3];
    __shared__ float ssc;
    __shared__ float pe[NC * 2];
    __shared__ float mnmx[4];
    __shared__ float ebd[NC * 2];
    int bg = blockIdx.x, b = bg >> 8, g = bg & 255, tid = threadIdx.x;

    if (tid < NC) {
        int pi = g_knn[bg * NC + tid];
        float4 q = g_pbb[b * NPTS + pi];
        px[tid] = q.x; py[tid] = q.y; pz[tid] = q.z;
    }
    __syncthreads();
    if (tid < 3) {
        const float* a = (tid == 0) ? px : ((tid == 1) ? py : pz);
        float s = 0.0f;
        for (int i = 0; i < NC; i++) s = __fadd_rn(s, a[i]);
        cen[tid] = __fdiv_rn(s, 64.0f);
    }
    __syncthreads();
    if (tid < NC) {
        float dx = __fsub_rn(px[tid], cen[0]);
        float dy = __fsub_rn(py[tid], cen[1]);
        float dz = __fsub_rn(pz[tid], cen[2]);
        nx[tid] = dx; ny[tid] = dy; nz[tid] = dz;
        nrm[tid] = __fsqrt_rn(__fadd_rn(__fadd_rn(__fmul_rn(dx, dx), __fmul_rn(dy, dy)), __fmul_rn(dz, dz)));
    }
    __syncthreads();
    if (tid == 0) {
        float m = nrm[0];
        for (int i = 1; i < NC; i++) m = fmaxf(m, nrm[i]);
        ssc = __fadd_rn(m, 1e-8f);
    }
    __syncthreads();
    if (tid < NC) {
        nx[tid] = __fdiv_rn(nx[tid], ssc);
        ny[tid] = __fdiv_rn(ny[tid], ssc);
        nz[tid] = __fdiv_rn(nz[tid], ssc);
    }
    __syncthreads();
    {   // s2pf encoder + maxpool
        int j = tid;
        float w0 = sew1[j], w1 = sew1[128 + j], w2 = sew1[256 + j], bb = seb1[j];
        float mx = 0.0f;
        for (int p = 0; p < NC; p++) {
            float a = __fmaf_rn(nz[p], w2, __fmaf_rn(ny[p], w1, __fmul_rn(nx[p], w0)));
            float hh = fmaxf(__fadd_rn(a, bb), 0.0f);
            mx = (p == 0) ? hh : fmaxf(mx, hh);
        }
        code[j] = mx;
    }
    __syncthreads();
    {   // h2 with hoisted code-dot
        int j = tid;
        float base = 0.0f;
        for (int k = 0; k < 128; k++) base = __fmaf_rn(code[k], sdw1[(3 + k) * 128 + j], base);
        float w0 = sdw1[j], w1 = sdw1[128 + j], w2 = sdw1[256 + j], bb = sdb1[j];
        for (int p = 0; p < NC; p++) {
            float a = __fadd_rn(__fmaf_rn(nz[p], w2, __fmaf_rn(ny[p], w1, __fmul_rn(nx[p], w0))), base);
            h2s[p * 129 + j] = fmaxf(__fadd_rn(a, bb), 0.0f);
        }
    }
    __syncthreads();
    {   // pe = h2 @ sd_w2 + b
        int p = tid & 63, c = tid >> 6;
        float s = 0.0f;
        for (int j = 0; j < 128; j++) s = __fmaf_rn(h2s[p * 129 + j], sdw2[j * 2 + c], s);
        pe[p * 2 + c] = __fadd_rn(s, sdb2[c]);
    }
    __syncthreads();
    if (tid < 2) {
        float mn = pe[tid], mx = pe[tid];
        for (int p = 1; p < NC; p++) { float v = pe[p * 2 + tid]; mn = fminf(mn, v); mx = fmaxf(mx, v); }
        mnmx[tid] = mn; mnmx[2 + tid] = mx;
    }
    __syncthreads();
    {
        int p = tid & 63, c = tid >> 6;
        const float HIL = (float)((1.0 - 1e-6) - 1e-6);
        float t = __fdiv_rn(__fsub_rn(pe[p * 2 + c], mnmx[c]),
                            __fadd_rn(__fsub_rn(mnmx[2 + c], mnmx[c]), 1e-8f));
        ebd[p * 2 + c] = __fadd_rn(__fmul_rn(t, HIL), 1e-6f);
    }
    __syncthreads();
    if (tid < 16) {   // per-cell nearest + assemble
        int k = tid;
        float gx = __fmul_rn((float)(k & 3) + 0.5f, 0.25f);
        float gy = __fmul_rn((float)(k >> 2) + 0.5f, 0.25f);
        float bd = 1e30f; int bi = 0;
        for (int p = 0; p < NC; p++) {
            float dx = __fsub_rn(gx, ebd[p * 2]);
            float dy = __fsub_rn(gy, ebd[p * 2 + 1]);
            float d2 = __fadd_rn(__fmul_rn(dx, dx), __fmul_rn(dy, dy));
            if (d2 < bd) { bd = d2; bi = p; }
        }
        int m = ((g >> 4) * 4 + (k >> 2)) * 64 + (g & 15) * 4 + (k & 3);
        float* o = out + ((long)b * 4096 + m) * 3;
        o[0] = px[bi]; o[1] = py[bi]; o[2] = pz[bi];
    }
}

extern "C" void kernel_launch(void* const* d_in, const int* in_sizes, int n_in,
                              void* d_out, int out_size) {
    const float* pts  = (const float*)d_in[0];
    const float* gew1 = (const float*)d_in[1];
    const float* geb1 = (const float*)d_in[2];
    const float* gew2 = (const float*)d_in[3];
    const float* geb2 = (const float*)d_in[4];
    const float* gdw1 = (const float*)d_in[5];
    const float* gdb1 = (const float*)d_in[6];
    const float* gdw2 = (const float*)d_in[7];
    const float* gdb2 = (const float*)d_in[8];
    const float* sew1 = (const float*)d_in[9];
    const float* seb1 = (const float*)d_in[10];
    const float* sdw1 = (const float*)d_in[11];
    const float* sdb1 = (const float*)d_in[12];
    const float* sdw2 = (const float*)d_in[13];
    const float* sdb2 = (const float*)d_in[14];
    float* out = (float*)d_out;

    k0_prep<<<BATCH * NPTS / 256, 256>>>(pts);
    k1_fps<<<BATCH * 8, 512>>>();
    k2_genc<<<BATCH * NG, 128>>>(gew1, geb1, gew2, geb2);
    k3a<<<BATCH, 256>>>(gdw1);
    k3b<<<BATCH * NG, 256>>>(gdw1, gdb1, gdw2, gdb2);
    k4_knn<<<BATCH * NG / 2, 256>>>();
    k5_patch<<<BATCH * NG, 128>>>(sew1, seb1, sdw1, sdb1, sdw2, sdb2, out);
}

// round 13
// speedup vs baseline: 1.3325x; 1.3325x over previous
#include <cuda_runtime.h>
#include <cstdint>

#define BATCH 8
#define NPTS  32768
#define NG    256
#define NC    64
#define KCAP  2048

__device__ float4 g_pbb[BATCH * NPTS];     // x,y,z,|p|^2 (square-then-add)
__device__ int    g_fps[BATCH * NG];
__device__ float  g_code[BATCH * 256];
__device__ float  g_cdot[BATCH * 256];
__device__ float  g_rec[BATCH * NG * 3];
__device__ int    g_knn[BATCH * NG * NC];

// ---------------- K0: SoA prep + zero code ----------------
__global__ void k0_prep(const float* __restrict__ pts) {
    int i = blockIdx.x * 256 + threadIdx.x;
    float x = pts[i * 3], y = pts[i * 3 + 1], z = pts[i * 3 + 2];
    float bb = __fadd_rn(__fadd_rn(__fmul_rn(x, x), __fmul_rn(y, y)), __fmul_rn(z, z));
    g_pbb[i] = make_float4(x, y, z, bb);
    if (i < BATCH * 256) g_code[i] = 0.0f;
}

// ---------------- K1: FPS — 8-CTA cluster per batch ----------------
// R9 structure (xyz carried in the DSMEM exchange, never re-fetched from L2),
// but: (a) warp/block argmax via redux.sync (dist>=0 so float order == uint
// bit order; min-idx tie-break via reduce_min over eligible lanes — idx is
// unique so exactly one writer lane), and (b) cluster sync via mbarrier with a
// SINGLE waiter thread (tid 0) + __syncthreads publish — avoids 512 threads
// spinning on try_wait (the R11/R12 regression) and the ~490cyc barrier.cluster.
// Exchange is double-buffered by iteration parity: any CTA's parity-p write at
// it+2 is ordered behind its phase-(it+1) wait, which is behind every CTA's
// arrive at it+1, which the block-reduce __syncthreads orders after that CTA's
// parity-p scan at it.
__global__ void __cluster_dims__(8, 1, 1) __launch_bounds__(512, 1) k1_fps() {
    __shared__ float s_wv[16];
    __shared__ int   s_wi[16];
    __shared__ float s_wx[16], s_wy[16], s_wz[16];
    __shared__ unsigned int s_rec[8];                         // CTA winner record
    __shared__ __align__(16) unsigned int s_exch[2][8 * 8];   // [parity][cta*8 words]
    __shared__ __align__(8) unsigned long long s_mb;

    int rank = blockIdx.x & 7;
    int b    = blockIdx.x >> 3;
    int tid  = threadIdx.x;
    int base = rank * 4096;

    const float4* __restrict__ pb = g_pbb + b * NPTS;

    float px[8], py[8], pz[8], dist[8];
#pragma unroll
    for (int j = 0; j < 8; j++) {
        float4 q = pb[base + tid + j * 512];
        px[j] = q.x; py[j] = q.y; pz[j] = q.z; dist[j] = 1e10f;
    }
    float4 q0 = pb[0];
    float sx = q0.x, sy = q0.y, sz = q0.z;
    int cur = 0;

    unsigned int mb  = (unsigned int)__cvta_generic_to_shared(&s_mb);
    unsigned int ex0 = (unsigned int)__cvta_generic_to_shared(&s_exch[0][0]);
    unsigned int ex1 = (unsigned int)__cvta_generic_to_shared(&s_exch[1][0]);

    if (tid == 0)
        asm volatile("mbarrier.init.shared.b64 [%0], 8;" :: "r"(mb) : "memory");
    asm volatile("barrier.cluster.arrive.aligned;" ::: "memory");
    asm volatile("barrier.cluster.wait.aligned;" ::: "memory");

    for (int it = 0; it < NG; it++) {
        if (rank == 0 && tid == 0) g_fps[b * NG + it] = cur;

        // per-thread local argmax over 8 points (strict > keeps lowest j,
        // and idx increases with j, so lowest-idx tie-break holds)
        unsigned int bb_ = 0u;
        int bj = 0;
#pragma unroll
        for (int j = 0; j < 8; j++) {
            float dx = __fsub_rn(px[j], sx), dy = __fsub_rn(py[j], sy), dz = __fsub_rn(pz[j], sz);
            float dd = __fadd_rn(__fadd_rn(__fmul_rn(dx, dx), __fmul_rn(dy, dy)), __fmul_rn(dz, dz));
            float nd = fminf(dist[j], dd);
            dist[j] = nd;
            unsigned int nb = __float_as_uint(nd);   // nd >= 0: bit order == float order
            if (nb > bb_) { bb_ = nb; bj = j; }
        }
        int bi = base + tid + bj * 512;
        float bx = px[0], by = py[0], bz = pz[0];
#pragma unroll
        for (int j = 1; j < 8; j++)
            if (j == bj) { bx = px[j]; by = py[j]; bz = pz[j]; }

        // warp argmax via redux.sync (exact, min-idx ties)
        unsigned int M  = __reduce_max_sync(0xffffffffu, bb_);
        unsigned int cd = (bb_ == M) ? (unsigned int)bi : 0xffffffffu;
        unsigned int wm = __reduce_min_sync(0xffffffffu, cd);
        if (bb_ == M && (unsigned int)bi == wm) {   // exactly one lane per warp
            int w = tid >> 5;
            s_wv[w] = __uint_as_float(M); s_wi[w] = (int)wm;
            s_wx[w] = bx; s_wy[w] = by; s_wz[w] = bz;
        }
        __syncthreads();

        if (tid < 32) {
            bool ok = tid < 16;
            unsigned int vb = ok ? __float_as_uint(s_wv[tid]) : 0u;
            int          ix = ok ? s_wi[tid] : 0x7fffffff;
            unsigned int M2 = __reduce_max_sync(0xffffffffu, vb);
            unsigned int c2 = (vb == M2) ? (unsigned int)ix : 0xffffffffu;
            unsigned int w2 = __reduce_min_sync(0xffffffffu, c2);
            if (ok && vb == M2 && (unsigned int)ix == w2) {
                s_rec[0] = M2; s_rec[1] = w2;
                s_rec[2] = __float_as_uint(s_wx[tid]);
                s_rec[3] = __float_as_uint(s_wy[tid]);
                s_rec[4] = __float_as_uint(s_wz[tid]);
            }
            __syncwarp();
            if (tid < 8) {
                unsigned int exb = (it & 1) ? ex1 : ex0;
                unsigned int v0 = s_rec[0], v1 = s_rec[1], v2 = s_rec[2],
                             v3 = s_rec[3], v4 = s_rec[4];
                unsigned int ra, rb;
                asm volatile("mapa.shared::cluster.u32 %0, %1, %2;"
                             : "=r"(ra) : "r"(exb + rank * 32), "r"(tid));
                asm volatile("st.shared::cluster.v4.b32 [%0], {%1,%2,%3,%4};"
                             :: "r"(ra), "r"(v0), "r"(v1), "r"(v2), "r"(v3) : "memory");
                asm volatile("st.shared::cluster.b32 [%0+16], %1;"
                             :: "r"(ra), "r"(v4) : "memory");
                asm volatile("mapa.shared::cluster.u32 %0, %1, %2;"
                             : "=r"(rb) : "r"(mb), "r"(tid));
                asm volatile("mbarrier.arrive.release.cluster.shared::cluster.b64 _, [%0];"
                             :: "r"(rb) : "memory");
            }
        }
        // SINGLE waiter, then publish to the CTA
        if (tid == 0) {
            unsigned int parity = (unsigned int)(it & 1);
            asm volatile(
                "{\n\t.reg .pred P;\n\t"
                "WL%=:\n\t"
                "mbarrier.try_wait.parity.acquire.cluster.shared::cta.b64 P, [%0], %1, 0x989680;\n\t"
                "@!P bra WL%=;\n\t}"
                :: "r"(mb), "r"(parity) : "memory");
        }
        __syncthreads();

        const unsigned int* e = s_exch[it & 1];
        float wv = -1.0f; int wi = 0x7fffffff;
        float nsx = sx, nsy = sy, nsz = sz;
#pragma unroll
        for (int r = 0; r < 8; r++) {
            float v = __uint_as_float(e[r * 8 + 0]);
            int   i = (int)e[r * 8 + 1];
            if (v > wv || (v == wv && i < wi)) {
                wv = v; wi = i;
                nsx = __uint_as_float(e[r * 8 + 2]);
                nsy = __uint_as_float(e[r * 8 + 3]);
                nsz = __uint_as_float(e[r * 8 + 4]);
            }
        }
        cur = wi; sx = nsx; sy = nsy; sz = nsz;
        __syncthreads();   // all scans of this parity done before next leader writes
    }
}

// ---------------- K2: g2sd encoder + maxpool ----------------
__global__ void __launch_bounds__(128) k2_genc(const float* __restrict__ w1, const float* __restrict__ b1,
                                               const float* __restrict__ w2, const float* __restrict__ b2) {
    __shared__ float h1[128];
    int bg = blockIdx.x, b = bg >> 8, j = threadIdx.x;
    int pi = g_fps[bg];
    float4 q = g_pbb[b * NPTS + pi];
    float a = __fmaf_rn(q.z, w1[256 + j], __fmaf_rn(q.y, w1[128 + j], __fmul_rn(q.x, w1[j])));
    h1[j] = fmaxf(__fadd_rn(a, b1[j]), 0.0f);
    __syncthreads();
#pragma unroll
    for (int t = 0; t < 2; t++) {
        int ch = j + t * 128;
        float s = 0.0f;
        for (int k = 0; k < 128; k++) s = __fmaf_rn(h1[k], w2[k * 256 + ch], s);
        float h2 = fmaxf(__fadd_rn(s, b2[ch]), 0.0f);
        atomicMax((int*)&g_code[b * 256 + ch], __float_as_int(h2));
    }
}

// ---------------- K3a: per-batch code @ gd_w1[2:,:] ----------------
__global__ void __launch_bounds__(256) k3a(const float* __restrict__ w1) {
    __shared__ float cs[256];
    int b = blockIdx.x, j = threadIdx.x;
    cs[j] = g_code[b * 256 + j];
    __syncthreads();
    float s = 0.0f;
    for (int k = 0; k < 256; k++) s = __fmaf_rn(cs[k], w1[(2 + k) * 256 + j], s);
    g_cdot[b * 256 + j] = s;
}

// ---------------- K3b: g2sd folding decoder -> rec_g ----------------
__global__ void __launch_bounds__(256) k3b(const float* __restrict__ w1, const float* __restrict__ b1,
                                           const float* __restrict__ w2, const float* __restrict__ b2) {
    __shared__ float h[256];
    int bg = blockIdx.x, b = bg >> 8, g = bg & 255, j = threadIdx.x;
    float gx = __fmul_rn((float)(g & 15) + 0.5f, 0.0625f);
    float gy = __fmul_rn((float)(g >> 4) + 0.5f, 0.0625f);
    float a = __fmaf_rn(gy, w1[256 + j], __fmul_rn(gx, w1[j]));
    a = __fadd_rn(a, g_cdot[b * 256 + j]);
    h[j] = fmaxf(__fadd_rn(a, b1[j]), 0.0f);
    __syncthreads();
    if (j < 3) {
        float s = 0.0f;
        for (int k = 0; k < 256; k++) s = __fmaf_rn(h[k], w2[k * 3 + j], s);
        g_rec[bg * 3 + j] = __fadd_rn(s, b2[j]);
    }
}

// ---------------- K4: exact 64-NN, threshold stream + pow2-sized bitonic compact ----------------
__global__ void __launch_bounds__(256) k4_knn() {
    __shared__ unsigned long long buf[KCAP];
    __shared__ int cnt, s_flag;
    __shared__ unsigned long long thr_s;
    int bg = blockIdx.x, b = bg >> 8, tid = threadIdx.x;
    float ax = g_rec[bg * 3], ay = g_rec[bg * 3 + 1], az = g_rec[bg * 3 + 2];
    float aa = __fadd_rn(__fadd_rn(__fmul_rn(ax, ax), __fmul_rn(ay, ay)), __fmul_rn(az, az));
    if (tid == 0) { cnt = 0; thr_s = ~0ULL; }
    __syncthreads();
    const float4* __restrict__ pb = g_pbb + b * NPTS;
    unsigned long long thr = ~0ULL;

    auto compact = [&]() {
        int c = cnt;                       // uniform (post-sync)
        int S = 64; while (S < c) S <<= 1; // pow2 >= c, >= 64  (c <= 1984 < KCAP)
        for (int t = tid; t < S; t += 256) if (t >= c) buf[t] = ~0ULL;
        __syncthreads();
        for (int k = 2; k <= S; k <<= 1)
            for (int j = k >> 1; j > 0; j >>= 1) {
                for (int t = tid; t < S; t += 256) {
                    int x = t ^ j;
                    if (x > t) {
                        unsigned long long A = buf[t], Bv = buf[x];
                        bool up = ((t & k) == 0);
                        if (up ? (A > Bv) : (A < Bv)) { buf[t] = Bv; buf[x] = A; }
                    }
                }
                __syncthreads();
            }
        if (tid == 0) { cnt = NC; thr_s = buf[NC - 1]; }
        __syncthreads();
    };

    for (int base = 0; base < NPTS; base += 1024) {
#pragma unroll
        for (int i = 0; i < 4; i++) {
            int p = base + tid + i * 256;
            float4 q = pb[p];
            float ab = __fmaf_rn(az, q.z, __fmaf_rn(ay, q.y, __fmul_rn(ax, q.x)));
            float dd = __fsub_rn(__fadd_rn(aa, q.w), __fmul_rn(2.0f, ab));
            unsigned int kb = __float_as_uint(dd);
            kb = (kb & 0x80000000u) ? ~kb : (kb | 0x80000000u);
            unsigned long long key = ((unsigned long long)kb << 32) | (unsigned int)p;
            if (key < thr) {
                int pos = atomicAdd(&cnt, 1);
                if (pos < KCAP) buf[pos] = key;
            }
        }
        __syncthreads();
        if (tid == 0) s_flag = (cnt > 960);
        __syncthreads();
        if (s_flag) { compact(); thr = thr_s; }
    }
    compact();
    if (tid < NC) g_knn[bg * NC + tid] = (int)(unsigned int)(buf[tid] & 0xffffffffu);
}

// ---------------- K5: normalize + s2pf + rescale + resample + assemble ----------------
__global__ void __launch_bounds__(128) k5_patch(const float* __restrict__ sew1, const float* __restrict__ seb1,
                                                const float* __restrict__ sdw1, const float* __restrict__ sdb1,
                                                const float* __restrict__ sdw2, const float* __restrict__ sdb2,
                                                float* __restrict__ out) {
    __shared__ float px[NC], py[NC], pz[NC];
    __shared__ float nx[NC], ny[NC], nz[NC], nrm[NC];
    __shared__ float code[128];
    __shared__ float h2s[NC * 129];
    __shared__ float cen[3];
    __shared__ float ssc;
    __shared__ float pe[NC * 2];
    __shared__ float mnmx[4];
    __shared__ float ebd[NC * 2];
    int bg = blockIdx.x, b = bg >> 8, g = bg & 255, tid = threadIdx.x;

    if (tid < NC) {
        int pi = g_knn[bg * NC + tid];
        float4 q = g_pbb[b * NPTS + pi];
        px[tid] = q.x; py[tid] = q.y; pz[tid] = q.z;
    }
    __syncthreads();
    if (tid < 3) {
        const float* a = (tid == 0) ? px : ((tid == 1) ? py : pz);
        float s = 0.0f;
        for (int i = 0; i < NC; i++) s = __fadd_rn(s, a[i]);
        cen[tid] = __fdiv_rn(s, 64.0f);
    }
    __syncthreads();
    if (tid < NC) {
        float dx = __fsub_rn(px[tid], cen[0]);
        float dy = __fsub_rn(py[tid], cen[1]);
        float dz = __fsub_rn(pz[tid], cen[2]);
        nx[tid] = dx; ny[tid] = dy; nz[tid] = dz;
        nrm[tid] = __fsqrt_rn(__fadd_rn(__fadd_rn(__fmul_rn(dx, dx), __fmul_rn(dy, dy)), __fmul_rn(dz, dz)));
    }
    __syncthreads();
    if (tid == 0) {
        float m = nrm[0];
        for (int i = 1; i < NC; i++) m = fmaxf(m, nrm[i]);
        ssc = __fadd_rn(m, 1e-8f);
    }
    __syncthreads();
    if (tid < NC) {
        nx[tid] = __fdiv_rn(nx[tid], ssc);
        ny[tid] = __fdiv_rn(ny[tid], ssc);
        nz[tid] = __fdiv_rn(nz[tid], ssc);
    }
    __syncthreads();
    {   // s2pf encoder + maxpool
        int j = tid;
        float w0 = sew1[j], w1 = sew1[128 + j], w2 = sew1[256 + j], bb = seb1[j];
        float mx = 0.0f;
        for (int p = 0; p < NC; p++) {
            float a = __fmaf_rn(nz[p], w2, __fmaf_rn(ny[p], w1, __fmul_rn(nx[p], w0)));
            float hh = fmaxf(__fadd_rn(a, bb), 0.0f);
            mx = (p == 0) ? hh : fmaxf(mx, hh);
        }
        code[j] = mx;
    }
    __syncthreads();
    {   // h2 with hoisted code-dot
        int j = tid;
        float base = 0.0f;
        for (int k = 0; k < 128; k++) base = __fmaf_rn(code[k], sdw1[(3 + k) * 128 + j], base);
        float w0 = sdw1[j], w1 = sdw1[128 + j], w2 = sdw1[256 + j], bb = sdb1[j];
        for (int p = 0; p < NC; p++) {
            float a = __fadd_rn(__fmaf_rn(nz[p], w2, __fmaf_rn(ny[p], w1, __fmul_rn(nx[p], w0))), base);
            h2s[p * 129 + j] = fmaxf(__fadd_rn(a, bb), 0.0f);
        }
    }
    __syncthreads();
    {   // pe = h2 @ sd_w2 + b
        int p = tid & 63, c = tid >> 6;
        float s = 0.0f;
        for (int j = 0; j < 128; j++) s = __fmaf_rn(h2s[p * 129 + j], sdw2[j * 2 + c], s);
        pe[p * 2 + c] = __fadd_rn(s, sdb2[c]);
    }
    __syncthreads();
    if (tid < 2) {
        float mn = pe[tid], mx = pe[tid];
        for (int p = 1; p < NC; p++) { float v = pe[p * 2 + tid]; mn = fminf(mn, v); mx = fmaxf(mx, v); }
        mnmx[tid] = mn; mnmx[2 + tid] = mx;
    }
    __syncthreads();
    {
        int p = tid & 63, c = tid >> 6;
        const float HIL = (float)((1.0 - 1e-6) - 1e-6);
        float t = __fdiv_rn(__fsub_rn(pe[p * 2 + c], mnmx[c]),
                            __fadd_rn(__fsub_rn(mnmx[2 + c], mnmx[c]), 1e-8f));
        ebd[p * 2 + c] = __fadd_rn(__fmul_rn(t, HIL), 1e-6f);
    }
    __syncthreads();
    if (tid < 16) {   // per-cell nearest + assemble
        int k = tid;
        float gx = __fmul_rn((float)(k & 3) + 0.5f, 0.25f);
        float gy = __fmul_rn((float)(k >> 2) + 0.5f, 0.25f);
        float bd = 1e30f; int bi = 0;
        for (int p = 0; p < NC; p++) {
            float dx = __fsub_rn(gx, ebd[p * 2]);
            float dy = __fsub_rn(gy, ebd[p * 2 + 1]);
            float d2 = __fadd_rn(__fmul_rn(dx, dx), __fmul_rn(dy, dy));
            if (d2 < bd) { bd = d2; bi = p; }
        }
        int m = ((g >> 4) * 4 + (k >> 2)) * 64 + (g & 15) * 4 + (k & 3);
        float* o = out + ((long)b * 4096 + m) * 3;
        o[0] = px[bi]; o[1] = py[bi]; o[2] = pz[bi];
    }
}

extern "C" void kernel_launch(void* const* d_in, const int* in_sizes, int n_in,
                              void* d_out, int out_size) {
    const float* pts  = (const float*)d_in[0];
    const float* gew1 = (const float*)d_in[1];
    const float* geb1 = (const float*)d_in[2];
    const float* gew2 = (const float*)d_in[3];
    const float* geb2 = (const float*)d_in[4];
    const float* gdw1 = (const float*)d_in[5];
    const float* gdb1 = (const float*)d_in[6];
    const float* gdw2 = (const float*)d_in[7];
    const float* gdb2 = (const float*)d_in[8];
    const float* sew1 = (const float*)d_in[9];
    const float* seb1 = (const float*)d_in[10];
    const float* sdw1 = (const float*)d_in[11];
    const float* sdb1 = (const float*)d_in[12];
    const float* sdw2 = (const float*)d_in[13];
    const float* sdb2 = (const float*)d_in[14];
    float* out = (float*)d_out;

    k0_prep<<<BATCH * NPTS / 256, 256>>>(pts);
    k1_fps<<<BATCH * 8, 512>>>();
    k2_genc<<<BATCH * NG, 128>>>(gew1, geb1, gew2, geb2);
    k3a<<<BATCH, 256>>>(gdw1);
    k3b<<<BATCH * NG, 256>>>(gdw1, gdb1, gdw2, gdb2);
    k4_knn<<<BATCH * NG, 256>>>();
    k5_patch<<<BATCH * NG, 128>>>(sew1, seb1, sdw1, sdb1, sdw2, sdb2, out);
}

// round 14
// speedup vs baseline: 1.4504x; 1.0884x over previous
#include <cuda_runtime.h>
#include <cstdint>

#define BATCH 8
#define NPTS  32768
#define NG    256
#define NC    64
#define KCAP  2048

__device__ float4 g_pbb[BATCH * NPTS];     // x,y,z,|p|^2 (square-then-add)
__device__ int    g_fps[BATCH * NG];
__device__ float  g_code[BATCH * 256];
__device__ float  g_cdot[BATCH * 256];
__device__ float  g_rec[BATCH * NG * 3];
__device__ int    g_knn[BATCH * NG * NC];

// ---------------- probes: shift the fixed ncu capture slot onto k1_fps ----------------
__global__ void probe_a() {}
__global__ void probe_b() {}

// ---------------- K0: SoA prep + zero code ----------------
__global__ void k0_prep(const float* __restrict__ pts) {
    int i = blockIdx.x * 256 + threadIdx.x;
    float x = pts[i * 3], y = pts[i * 3 + 1], z = pts[i * 3 + 2];
    float bb = __fadd_rn(__fadd_rn(__fmul_rn(x, x), __fmul_rn(y, y)), __fmul_rn(z, z));
    g_pbb[i] = make_float4(x, y, z, bb);
    if (i < BATCH * 256) g_code[i] = 0.0f;
}

// ---------------- K1: FPS — 8-CTA cluster per batch ----------------
// R9 structure (xyz carried in the DSMEM exchange, barrier.cluster per iter —
// the proven-fastest sync), with the only change being redux.sync argmax:
// dist >= 0 so float order == uint bit order; reduce_max over bits, then
// reduce_min over candidate global indices = exact lowest-index tie-break,
// and index uniqueness guarantees exactly one writer lane per warp.
__global__ void __cluster_dims__(8, 1, 1) __launch_bounds__(512, 1) k1_fps() {
    __shared__ float s_wv[16];
    __shared__ int   s_wi[16];
    __shared__ float s_wx[16], s_wy[16], s_wz[16];
    __shared__ unsigned int s_rec[8];                         // CTA winner record
    __shared__ __align__(16) unsigned int s_exch[2][8 * 8];   // [parity][cta*8 words]

    int rank = blockIdx.x & 7;
    int b    = blockIdx.x >> 3;
    int tid  = threadIdx.x;
    int base = rank * 4096;

    const float4* __restrict__ pb = g_pbb + b * NPTS;

    float px[8], py[8], pz[8], dist[8];
#pragma unroll
    for (int j = 0; j < 8; j++) {
        float4 q = pb[base + tid + j * 512];
        px[j] = q.x; py[j] = q.y; pz[j] = q.z; dist[j] = 1e10f;
    }
    float4 q0 = pb[0];
    float sx = q0.x, sy = q0.y, sz = q0.z;
    int cur = 0;

    unsigned int ex0 = (unsigned int)__cvta_generic_to_shared(&s_exch[0][0]);
    unsigned int ex1 = (unsigned int)__cvta_generic_to_shared(&s_exch[1][0]);

    for (int it = 0; it < NG; it++) {
        if (rank == 0 && tid == 0) g_fps[b * NG + it] = cur;

        // per-thread argmax over 8 points (strict > keeps lowest j; idx grows
        // with j so lowest-index tie-break holds)
        unsigned int bb_ = 0u;
        int bj = 0;
#pragma unroll
        for (int j = 0; j < 8; j++) {
            float dx = __fsub_rn(px[j], sx), dy = __fsub_rn(py[j], sy), dz = __fsub_rn(pz[j], sz);
            float dd = __fadd_rn(__fadd_rn(__fmul_rn(dx, dx), __fmul_rn(dy, dy)), __fmul_rn(dz, dz));
            float nd = fminf(dist[j], dd);
            dist[j] = nd;
            unsigned int nb = __float_as_uint(nd);
            if (nb > bb_) { bb_ = nb; bj = j; }
        }
        int bi = base + tid + bj * 512;
        float bx = px[0], by = py[0], bz = pz[0];
#pragma unroll
        for (int j = 1; j < 8; j++)
            if (j == bj) { bx = px[j]; by = py[j]; bz = pz[j]; }

        // warp argmax via redux.sync
        unsigned int M  = __reduce_max_sync(0xffffffffu, bb_);
        unsigned int cd = (bb_ == M) ? (unsigned int)bi : 0xffffffffu;
        unsigned int wm = __reduce_min_sync(0xffffffffu, cd);
        if (bb_ == M && (unsigned int)bi == wm) {   // exactly one lane per warp
            int w = tid >> 5;
            s_wv[w] = __uint_as_float(M); s_wi[w] = (int)wm;
            s_wx[w] = bx; s_wy[w] = by; s_wz[w] = bz;
        }
        __syncthreads();

        if (tid < 32) {
            bool ok = tid < 16;
            unsigned int vb = ok ? __float_as_uint(s_wv[tid]) : 0u;
            int          ix = ok ? s_wi[tid] : 0x7fffffff;
            unsigned int M2 = __reduce_max_sync(0xffffffffu, vb);
            unsigned int c2 = (vb == M2) ? (unsigned int)ix : 0xffffffffu;
            unsigned int w2 = __reduce_min_sync(0xffffffffu, c2);
            if (ok && vb == M2 && (unsigned int)ix == w2) {
                s_rec[0] = M2; s_rec[1] = w2;
                s_rec[2] = __float_as_uint(s_wx[tid]);
                s_rec[3] = __float_as_uint(s_wy[tid]);
                s_rec[4] = __float_as_uint(s_wz[tid]);
            }
            __syncwarp();
            if (tid < 8) {
                unsigned int exb = (it & 1) ? ex1 : ex0;
                unsigned int v0 = s_rec[0], v1 = s_rec[1], v2 = s_rec[2],
                             v3 = s_rec[3], v4 = s_rec[4];
                unsigned int ra;
                asm volatile("mapa.shared::cluster.u32 %0, %1, %2;"
                             : "=r"(ra) : "r"(exb + rank * 32), "r"(tid));
                asm volatile("st.shared::cluster.v4.b32 [%0], {%1,%2,%3,%4};"
                             :: "r"(ra), "r"(v0), "r"(v1), "r"(v2), "r"(v3) : "memory");
                asm volatile("st.shared::cluster.b32 [%0+16], %1;"
                             :: "r"(ra), "r"(v4) : "memory");
            }
        }
        asm volatile("barrier.cluster.arrive.aligned;" ::: "memory");
        asm volatile("barrier.cluster.wait.aligned;" ::: "memory");

        // all threads pick the cluster-wide winner identically
        const unsigned int* e = s_exch[it & 1];
        float wv = -1.0f; int wi = 0x7fffffff;
        float nsx = sx, nsy = sy, nsz = sz;
#pragma unroll
        for (int r = 0; r < 8; r++) {
            float v = __uint_as_float(e[r * 8 + 0]);
            int   i = (int)e[r * 8 + 1];
            if (v > wv || (v == wv && i < wi)) {
                wv = v; wi = i;
                nsx = __uint_as_float(e[r * 8 + 2]);
                nsy = __uint_as_float(e[r * 8 + 3]);
                nsz = __uint_as_float(e[r * 8 + 4]);
            }
        }
        cur = wi; sx = nsx; sy = nsy; sz = nsz;
        // no trailing __syncthreads: the next write to s_wv/s_exch[parity] is
        // separated from these reads by the block-wide barrier.cluster above
        // (next iteration) plus the __syncthreads after the warp stage.
    }
}

// ---------------- K2: g2sd encoder + maxpool ----------------
__global__ void __launch_bounds__(128) k2_genc(const float* __restrict__ w1, const float* __restrict__ b1,
                                               const float* __restrict__ w2, const float* __restrict__ b2) {
    __shared__ float h1[128];
    int bg = blockIdx.x, b = bg >> 8, j = threadIdx.x;
    int pi = g_fps[bg];
    float4 q = g_pbb[b * NPTS + pi];
    float a = __fmaf_rn(q.z, w1[256 + j], __fmaf_rn(q.y, w1[128 + j], __fmul_rn(q.x, w1[j])));
    h1[j] = fmaxf(__fadd_rn(a, b1[j]), 0.0f);
    __syncthreads();
#pragma unroll
    for (int t = 0; t < 2; t++) {
        int ch = j + t * 128;
        float s = 0.0f;
        for (int k = 0; k < 128; k++) s = __fmaf_rn(h1[k], w2[k * 256 + ch], s);
        float h2 = fmaxf(__fadd_rn(s, b2[ch]), 0.0f);
        atomicMax((int*)&g_code[b * 256 + ch], __float_as_int(h2));
    }
}

// ---------------- K3a: per-batch code @ gd_w1[2:,:] ----------------
__global__ void __launch_bounds__(256) k3a(const float* __restrict__ w1) {
    __shared__ float cs[256];
    int b = blockIdx.x, j = threadIdx.x;
    cs[j] = g_code[b * 256 + j];
    __syncthreads();
    float s = 0.0f;
    for (int k = 0; k < 256; k++) s = __fmaf_rn(cs[k], w1[(2 + k) * 256 + j], s);
    g_cdot[b * 256 + j] = s;
}

// ---------------- K3b: g2sd folding decoder -> rec_g ----------------
__global__ void __launch_bounds__(256) k3b(const float* __restrict__ w1, const float* __restrict__ b1,
                                           const float* __restrict__ w2, const float* __restrict__ b2) {
    __shared__ float h[256];
    int bg = blockIdx.x, b = bg >> 8, g = bg & 255, j = threadIdx.x;
    float gx = __fmul_rn((float)(g & 15) + 0.5f, 0.0625f);
    float gy = __fmul_rn((float)(g >> 4) + 0.5f, 0.0625f);
    float a = __fmaf_rn(gy, w1[256 + j], __fmul_rn(gx, w1[j]));
    a = __fadd_rn(a, g_cdot[b * 256 + j]);
    h[j] = fmaxf(__fadd_rn(a, b1[j]), 0.0f);
    __syncthreads();
    if (j < 3) {
        float s = 0.0f;
        for (int k = 0; k < 256; k++) s = __fmaf_rn(h[k], w2[k * 3 + j], s);
        g_rec[bg * 3 + j] = __fadd_rn(s, b2[j]);
    }
}

// ---------------- K4: exact 64-NN, threshold stream + pow2-sized bitonic compact ----------------
__global__ void __launch_bounds__(256) k4_knn() {
    __shared__ unsigned long long buf[KCAP];
    __shared__ int cnt, s_flag;
    __shared__ unsigned long long thr_s;
    int bg = blockIdx.x, b = bg >> 8, tid = threadIdx.x;
    float ax = g_rec[bg * 3], ay = g_rec[bg * 3 + 1], az = g_rec[bg * 3 + 2];
    float aa = __fadd_rn(__fadd_rn(__fmul_rn(ax, ax), __fmul_rn(ay, ay)), __fmul_rn(az, az));
    if (tid == 0) { cnt = 0; thr_s = ~0ULL; }
    __syncthreads();
    const float4* __restrict__ pb = g_pbb + b * NPTS;
    unsigned long long thr = ~0ULL;

    auto compact = [&]() {
        int c = cnt;                       // uniform (post-sync)
        int S = 64; while (S < c) S <<= 1; // pow2 >= c, >= 64  (c <= 1984 < KCAP)
        for (int t = tid; t < S; t += 256) if (t >= c) buf[t] = ~0ULL;
        __syncthreads();
        for (int k = 2; k <= S; k <<= 1)
            for (int j = k >> 1; j > 0; j >>= 1) {
                for (int t = tid; t < S; t += 256) {
                    int x = t ^ j;
                    if (x > t) {
                        unsigned long long A = buf[t], Bv = buf[x];
                        bool up = ((t & k) == 0);
                        if (up ? (A > Bv) : (A < Bv)) { buf[t] = Bv; buf[x] = A; }
                    }
                }
                __syncthreads();
            }
        if (tid == 0) { cnt = NC; thr_s = buf[NC - 1]; }
        __syncthreads();
    };

    for (int base = 0; base < NPTS; base += 1024) {
#pragma unroll
        for (int i = 0; i < 4; i++) {
            int p = base + tid + i * 256;
            float4 q = pb[p];
            float ab = __fmaf_rn(az, q.z, __fmaf_rn(ay, q.y, __fmul_rn(ax, q.x)));
            float dd = __fsub_rn(__fadd_rn(aa, q.w), __fmul_rn(2.0f, ab));
            unsigned int kb = __float_as_uint(dd);
            kb = (kb & 0x80000000u) ? ~kb : (kb | 0x80000000u);
            unsigned long long key = ((unsigned long long)kb << 32) | (unsigned int)p;
            if (key < thr) {
                int pos = atomicAdd(&cnt, 1);
                if (pos < KCAP) buf[pos] = key;
            }
        }
        __syncthreads();
        if (tid == 0) s_flag = (cnt > 960);
        __syncthreads();
        if (s_flag) { compact(); thr = thr_s; }
    }
    compact();
    if (tid < NC) g_knn[bg * NC + tid] = (int)(unsigned int)(buf[tid] & 0xffffffffu);
}

// ---------------- K5: normalize + s2pf + rescale + resample + assemble ----------------
__global__ void __launch_bounds__(128) k5_patch(const float* __restrict__ sew1, const float* __restrict__ seb1,
                                                const float* __restrict__ sdw1, const float* __restrict__ sdb1,
                                                const float* __restrict__ sdw2, const float* __restrict__ sdb2,
                                                float* __restrict__ out) {
    __shared__ float px[NC], py[NC], pz[NC];
    __shared__ float nx[NC], ny[NC], nz[NC], nrm[NC];
    __shared__ float code[128];
    __shared__ float h2s[NC * 129];
    __shared__ float cen[3];
    __shared__ float ssc;
    __shared__ float pe[NC * 2];
    __shared__ float mnmx[4];
    __shared__ float ebd[NC * 2];
    int bg = blockIdx.x, b = bg >> 8, g = bg & 255, tid = threadIdx.x;

    if (tid < NC) {
        int pi = g_knn[bg * NC + tid];
        float4 q = g_pbb[b * NPTS + pi];
        px[tid] = q.x; py[tid] = q.y; pz[tid] = q.z;
    }
    __syncthreads();
    if (tid < 3) {
        const float* a = (tid == 0) ? px : ((tid == 1) ? py : pz);
        float s = 0.0f;
        for (int i = 0; i < NC; i++) s = __fadd_rn(s, a[i]);
        cen[tid] = __fdiv_rn(s, 64.0f);
    }
    __syncthreads();
    if (tid < NC) {
        float dx = __fsub_rn(px[tid], cen[0]);
        float dy = __fsub_rn(py[tid], cen[1]);
        float dz = __fsub_rn(pz[tid], cen[2]);
        nx[tid] = dx; ny[tid] = dy; nz[tid] = dz;
        nrm[tid] = __fsqrt_rn(__fadd_rn(__fadd_rn(__fmul_rn(dx, dx), __fmul_rn(dy, dy)), __fmul_rn(dz, dz)));
    }
    __syncthreads();
    if (tid == 0) {
        float m = nrm[0];
        for (int i = 1; i < NC; i++) m = fmaxf(m, nrm[i]);
        ssc = __fadd_rn(m, 1e-8f);
    }
    __syncthreads();
    if (tid < NC) {
        nx[tid] = __fdiv_rn(nx[tid], ssc);
        ny[tid] = __fdiv_rn(ny[tid], ssc);
        nz[tid] = __fdiv_rn(nz[tid], ssc);
    }
    __syncthreads();
    {   // s2pf encoder + maxpool
        int j = tid;
        float w0 = sew1[j], w1 = sew1[128 + j], w2 = sew1[256 + j], bb = seb1[j];
        float mx = 0.0f;
        for (int p = 0; p < NC; p++) {
            float a = __fmaf_rn(nz[p], w2, __fmaf_rn(ny[p], w1, __fmul_rn(nx[p], w0)));
            float hh = fmaxf(__fadd_rn(a, bb), 0.0f);
            mx = (p == 0) ? hh : fmaxf(mx, hh);
        }
        code[j] = mx;
    }
    __syncthreads();
    {   // h2 with hoisted code-dot
        int j = tid;
        float base = 0.0f;
        for (int k = 0; k < 128; k++) base = __fmaf_rn(code[k], sdw1[(3 + k) * 128 + j], base);
        float w0 = sdw1[j], w1 = sdw1[128 + j], w2 = sdw1[256 + j], bb = sdb1[j];
        for (int p = 0; p < NC; p++) {
            float a = __fadd_rn(__fmaf_rn(nz[p], w2, __fmaf_rn(ny[p], w1, __fmul_rn(nx[p], w0))), base);
            h2s[p * 129 + j] = fmaxf(__fadd_rn(a, bb), 0.0f);
        }
    }
    __syncthreads();
    {   // pe = h2 @ sd_w2 + b
        int p = tid & 63, c = tid >> 6;
        float s = 0.0f;
        for (int j = 0; j < 128; j++) s = __fmaf_rn(h2s[p * 129 + j], sdw2[j * 2 + c], s);
        pe[p * 2 + c] = __fadd_rn(s, sdb2[c]);
    }
    __syncthreads();
    if (tid < 2) {
        float mn = pe[tid], mx = pe[tid];
        for (int p = 1; p < NC; p++) { float v = pe[p * 2 + tid]; mn = fminf(mn, v); mx = fmaxf(mx, v); }
        mnmx[tid] = mn; mnmx[2 + tid] = mx;
    }
    __syncthreads();
    {
        int p = tid & 63, c = tid >> 6;
        const float HIL = (float)((1.0 - 1e-6) - 1e-6);
        float t = __fdiv_rn(__fsub_rn(pe[p * 2 + c], mnmx[c]),
                            __fadd_rn(__fsub_rn(mnmx[2 + c], mnmx[c]), 1e-8f));
        ebd[p * 2 + c] = __fadd_rn(__fmul_rn(t, HIL), 1e-6f);
    }
    __syncthreads();
    if (tid < 16) {   // per-cell nearest + assemble
        int k = tid;
        float gx = __fmul_rn((float)(k & 3) + 0.5f, 0.25f);
        float gy = __fmul_rn((float)(k >> 2) + 0.5f, 0.25f);
        float bd = 1e30f; int bi = 0;
        for (int p = 0; p < NC; p++) {
            float dx = __fsub_rn(gx, ebd[p * 2]);
            float dy = __fsub_rn(gy, ebd[p * 2 + 1]);
            float d2 = __fadd_rn(__fmul_rn(dx, dx), __fmul_rn(dy, dy));
            if (d2 < bd) { bd = d2; bi = p; }
        }
        int m = ((g >> 4) * 4 + (k >> 2)) * 64 + (g & 15) * 4 + (k & 3);
        float* o = out + ((long)b * 4096 + m) * 3;
        o[0] = px[bi]; o[1] = py[bi]; o[2] = pz[bi];
    }
}

extern "C" void kernel_launch(void* const* d_in, const int* in_sizes, int n_in,
                              void* d_out, int out_size) {
    const float* pts  = (const float*)d_in[0];
    const float* gew1 = (const float*)d_in[1];
    const float* geb1 = (const float*)d_in[2];
    const float* gew2 = (const float*)d_in[3];
    const float* geb2 = (const float*)d_in[4];
    const float* gdw1 = (const float*)d_in[5];
    const float* gdb1 = (const float*)d_in[6];
    const float* gdw2 = (const float*)d_in[7];
    const float* gdb2 = (const float*)d_in[8];
    const float* sew1 = (const float*)d_in[9];
    const float* seb1 = (const float*)d_in[10];
    const float* sdw1 = (const float*)d_in[11];
    const float* sdb1 = (const float*)d_in[12];
    const float* sdw2 = (const float*)d_in[13];
    const float* sdb2 = (const float*)d_in[14];
    float* out = (float*)d_out;

    // probes shift the fixed ncu capture slot (previously landing on k3a,
    // our 4th launch) onto k1_fps
    probe_a<<<1, 32>>>();
    probe_b<<<1, 32>>>();
    k0_prep<<<BATCH * NPTS / 256, 256>>>(pts);
    k1_fps<<<BATCH * 8, 512>>>();
    k2_genc<<<BATCH * NG, 128>>>(gew1, geb1, gew2, geb2);
    k3a<<<BATCH, 256>>>(gdw1);
    k3b<<<BATCH * NG, 256>>>(gdw1, gdb1, gdw2, gdb2);
    k4_knn<<<BATCH * NG, 256>>>();
    k5_patch<<<BATCH * NG, 128>>>(sew1, seb1, sdw1, sdb1, sdw2, sdb2, out);
}

// round 15
// speedup vs baseline: 1.4550x; 1.0032x over previous
#include <cuda_runtime.h>
#include <cstdint>

#define BATCH 8
#define NPTS  32768
#define NG    256
#define NC    64
#define KCAP  2048

__device__ float4 g_pbb[BATCH * NPTS];     // x,y,z,|p|^2 (square-then-add)
__device__ int    g_fps[BATCH * NG];
__device__ float  g_code[BATCH * 256];
__device__ float  g_cdot[BATCH * 256];
__device__ float  g_rec[BATCH * NG * 3];
__device__ int    g_knn[BATCH * NG * NC];

#define PACK2(out, lo, hi) \
    asm("mov.b64 %0, {%1, %2};" : "=l"(out) : "f"(lo), "f"(hi))
#define ADD2(out, a, b) \
    asm("add.rn.f32x2 %0, %1, %2;" : "=l"(out) : "l"(a), "l"(b))
#define MUL2(out, a, b) \
    asm("mul.rn.f32x2 %0, %1, %2;" : "=l"(out) : "l"(a), "l"(b))

// ---------------- probes: keep the fixed ncu capture slot on k1_fps ----------------
__global__ void probe_a() {}
__global__ void probe_b() {}

// ---------------- K0: SoA prep + zero code ----------------
__global__ void k0_prep(const float* __restrict__ pts) {
    int i = blockIdx.x * 256 + threadIdx.x;
    float x = pts[i * 3], y = pts[i * 3 + 1], z = pts[i * 3 + 2];
    float bb = __fadd_rn(__fadd_rn(__fmul_rn(x, x), __fmul_rn(y, y)), __fmul_rn(z, z));
    g_pbb[i] = make_float4(x, y, z, bb);
    if (i < BATCH * 256) g_code[i] = 0.0f;
}

// ---------------- K1: FPS — 8-CTA cluster per batch, f32x2-packed update ----------------
// R14 structure (DSMEM xyz exchange + barrier.cluster + redux.sync argmax).
// Distance update vectorized with packed f32x2: per point-pair, 3 add (p+(-s);
// IEEE x-y == x+(-y) exactly), 3 mul (squares), 2 add (sum) — lane-wise .rn is
// bit-identical to the scalar __fadd_rn/__fmul_rn chain. min/argmax run as
// integer ops on dist bits (dd >= 0 so uint order == float order), shifting
// that work to the ALU pipe.
__global__ void __cluster_dims__(8, 1, 1) __launch_bounds__(512, 1) k1_fps() {
    __shared__ float s_wv[16];
    __shared__ int   s_wi[16];
    __shared__ float s_wx[16], s_wy[16], s_wz[16];
    __shared__ unsigned int s_rec[8];                         // CTA winner record
    __shared__ __align__(16) unsigned int s_exch[2][8 * 8];   // [parity][cta*8 words]

    int rank = blockIdx.x & 7;
    int b    = blockIdx.x >> 3;
    int tid  = threadIdx.x;
    int base = rank * 4096;

    const float4* __restrict__ pb = g_pbb + b * NPTS;

    // packed point storage: pair m holds points j=2m (lo lane) and j=2m+1 (hi lane)
    unsigned long long px2[4], py2[4], pz2[4];
    unsigned int du[8];
#pragma unroll
    for (int m = 0; m < 4; m++) {
        float4 qa = pb[base + tid + (2 * m) * 512];
        float4 qb = pb[base + tid + (2 * m + 1) * 512];
        PACK2(px2[m], qa.x, qb.x);
        PACK2(py2[m], qa.y, qb.y);
        PACK2(pz2[m], qa.z, qb.z);
        du[2 * m] = du[2 * m + 1] = __float_as_uint(1e10f);
    }
    float4 q0 = pb[0];
    float sx = q0.x, sy = q0.y, sz = q0.z;
    int cur = 0;

    unsigned int ex0 = (unsigned int)__cvta_generic_to_shared(&s_exch[0][0]);
    unsigned int ex1 = (unsigned int)__cvta_generic_to_shared(&s_exch[1][0]);

    for (int it = 0; it < NG; it++) {
        if (rank == 0 && tid == 0) g_fps[b * NG + it] = cur;

        float nsx = -sx, nsy = -sy, nsz = -sz;   // negation is exact
        unsigned long long nsx2, nsy2, nsz2;
        PACK2(nsx2, nsx, nsx);
        PACK2(nsy2, nsy, nsy);
        PACK2(nsz2, nsz, nsz);

        unsigned int bb_ = 0u;
        int bj = 0;
#pragma unroll
        for (int m = 0; m < 4; m++) {
            unsigned long long dx, dy, dz, xx, yy, zz, s;
            ADD2(dx, px2[m], nsx2);
            ADD2(dy, py2[m], nsy2);
            ADD2(dz, pz2[m], nsz2);
            MUL2(xx, dx, dx);
            MUL2(yy, dy, dy);
            MUL2(zz, dz, dz);
            ADD2(s, xx, yy);
            ADD2(s, s, zz);
            unsigned int lo = (unsigned int)s;
            unsigned int hi = (unsigned int)(s >> 32);
            unsigned int n0 = min(du[2 * m], lo);       // uint order == float order (>=0)
            du[2 * m] = n0;
            if (n0 > bb_) { bb_ = n0; bj = 2 * m; }     // strict >: lowest index on ties
            unsigned int n1 = min(du[2 * m + 1], hi);
            du[2 * m + 1] = n1;
            if (n1 > bb_) { bb_ = n1; bj = 2 * m + 1; }
        }
        int bi = base + tid + bj * 512;
        float bx, by, bz;
        {
            unsigned long long X = px2[bj >> 1], Y = py2[bj >> 1], Z = pz2[bj >> 1];
            if (bj & 1) {
                bx = __uint_as_float((unsigned int)(X >> 32));
                by = __uint_as_float((unsigned int)(Y >> 32));
                bz = __uint_as_float((unsigned int)(Z >> 32));
            } else {
                bx = __uint_as_float((unsigned int)X);
                by = __uint_as_float((unsigned int)Y);
                bz = __uint_as_float((unsigned int)Z);
            }
        }

        // warp argmax via redux.sync (exact, min-idx ties; idx unique -> one writer)
        unsigned int M  = __reduce_max_sync(0xffffffffu, bb_);
        unsigned int cd = (bb_ == M) ? (unsigned int)bi : 0xffffffffu;
        unsigned int wm = __reduce_min_sync(0xffffffffu, cd);
        if (bb_ == M && (unsigned int)bi == wm) {
            int w = tid >> 5;
            s_wv[w] = __uint_as_float(M); s_wi[w] = (int)wm;
            s_wx[w] = bx; s_wy[w] = by; s_wz[w] = bz;
        }
        __syncthreads();

        if (tid < 32) {
            bool ok = tid < 16;
            unsigned int vb = ok ? __float_as_uint(s_wv[tid]) : 0u;
            int          ix = ok ? s_wi[tid] : 0x7fffffff;
            unsigned int M2 = __reduce_max_sync(0xffffffffu, vb);
            unsigned int c2 = (vb == M2) ? (unsigned int)ix : 0xffffffffu;
            unsigned int w2 = __reduce_min_sync(0xffffffffu, c2);
            if (ok && vb == M2 && (unsigned int)ix == w2) {
                s_rec[0] = M2; s_rec[1] = w2;
                s_rec[2] = __float_as_uint(s_wx[tid]);
                s_rec[3] = __float_as_uint(s_wy[tid]);
                s_rec[4] = __float_as_uint(s_wz[tid]);
            }
            __syncwarp();
            if (tid < 8) {
                unsigned int exb = (it & 1) ? ex1 : ex0;
                unsigned int v0 = s_rec[0], v1 = s_rec[1], v2 = s_rec[2],
                             v3 = s_rec[3], v4 = s_rec[4];
                unsigned int ra;
                asm volatile("mapa.shared::cluster.u32 %0, %1, %2;"
                             : "=r"(ra) : "r"(exb + rank * 32), "r"(tid));
                asm volatile("st.shared::cluster.v4.b32 [%0], {%1,%2,%3,%4};"
                             :: "r"(ra), "r"(v0), "r"(v1), "r"(v2), "r"(v3) : "memory");
                asm volatile("st.shared::cluster.b32 [%0+16], %1;"
                             :: "r"(ra), "r"(v4) : "memory");
            }
        }
        asm volatile("barrier.cluster.arrive.aligned;" ::: "memory");
        asm volatile("barrier.cluster.wait.aligned;" ::: "memory");

        const unsigned int* e = s_exch[it & 1];
        float wv = -1.0f; int wi = 0x7fffffff;
        float nsx_ = sx, nsy_ = sy, nsz_ = sz;
#pragma unroll
        for (int r = 0; r < 8; r++) {
            float v = __uint_as_float(e[r * 8 + 0]);
            int   i = (int)e[r * 8 + 1];
            if (v > wv || (v == wv && i < wi)) {
                wv = v; wi = i;
                nsx_ = __uint_as_float(e[r * 8 + 2]);
                nsy_ = __uint_as_float(e[r * 8 + 3]);
                nsz_ = __uint_as_float(e[r * 8 + 4]);
            }
        }
        cur = wi; sx = nsx_; sy = nsy_; sz = nsz_;
    }
}

// ---------------- K2: g2sd encoder + maxpool ----------------
__global__ void __launch_bounds__(128) k2_genc(const float* __restrict__ w1, const float* __restrict__ b1,
                                               const float* __restrict__ w2, const float* __restrict__ b2) {
    __shared__ float h1[128];
    int bg = blockIdx.x, b = bg >> 8, j = threadIdx.x;
    int pi = g_fps[bg];
    float4 q = g_pbb[b * NPTS + pi];
    float a = __fmaf_rn(q.z, w1[256 + j], __fmaf_rn(q.y, w1[128 + j], __fmul_rn(q.x, w1[j])));
    h1[j] = fmaxf(__fadd_rn(a, b1[j]), 0.0f);
    __syncthreads();
#pragma unroll
    for (int t = 0; t < 2; t++) {
        int ch = j + t * 128;
        float s = 0.0f;
        for (int k = 0; k < 128; k++) s = __fmaf_rn(h1[k], w2[k * 256 + ch], s);
        float h2 = fmaxf(__fadd_rn(s, b2[ch]), 0.0f);
        atomicMax((int*)&g_code[b * 256 + ch], __float_as_int(h2));
    }
}

// ---------------- K3a: per-batch code @ gd_w1[2:,:] ----------------
__global__ void __launch_bounds__(256) k3a(const float* __restrict__ w1) {
    __shared__ float cs[256];
    int b = blockIdx.x, j = threadIdx.x;
    cs[j] = g_code[b * 256 + j];
    __syncthreads();
    float s = 0.0f;
    for (int k = 0; k < 256; k++) s = __fmaf_rn(cs[k], w1[(2 + k) * 256 + j], s);
    g_cdot[b * 256 + j] = s;
}

// ---------------- K3b: g2sd folding decoder -> rec_g ----------------
__global__ void __launch_bounds__(256) k3b(const float* __restrict__ w1, const float* __restrict__ b1,
                                           const float* __restrict__ w2, const float* __restrict__ b2) {
    __shared__ float h[256];
    int bg = blockIdx.x, b = bg >> 8, g = bg & 255, j = threadIdx.x;
    float gx = __fmul_rn((float)(g & 15) + 0.5f, 0.0625f);
    float gy = __fmul_rn((float)(g >> 4) + 0.5f, 0.0625f);
    float a = __fmaf_rn(gy, w1[256 + j], __fmul_rn(gx, w1[j]));
    a = __fadd_rn(a, g_cdot[b * 256 + j]);
    h[j] = fmaxf(__fadd_rn(a, b1[j]), 0.0f);
    __syncthreads();
    if (j < 3) {
        float s = 0.0f;
        for (int k = 0; k < 256; k++) s = __fmaf_rn(h[k], w2[k * 3 + j], s);
        g_rec[bg * 3 + j] = __fadd_rn(s, b2[j]);
    }
}

// ---------------- K4: exact 64-NN, threshold stream + pow2-sized bitonic compact ----------------
__global__ void __launch_bounds__(256) k4_knn() {
    __shared__ unsigned long long buf[KCAP];
    __shared__ int cnt, s_flag;
    __shared__ unsigned long long thr_s;
    int bg = blockIdx.x, b = bg >> 8, tid = threadIdx.x;
    float ax = g_rec[bg * 3], ay = g_rec[bg * 3 + 1], az = g_rec[bg * 3 + 2];
    float aa = __fadd_rn(__fadd_rn(__fmul_rn(ax, ax), __fmul_rn(ay, ay)), __fmul_rn(az, az));
    if (tid == 0) { cnt = 0; thr_s = ~0ULL; }
    __syncthreads();
    const float4* __restrict__ pb = g_pbb + b * NPTS;
    unsigned long long thr = ~0ULL;

    auto compact = [&]() {
        int c = cnt;                       // uniform (post-sync)
        int S = 64; while (S < c) S <<= 1; // pow2 >= c, >= 64  (c <= 1984 < KCAP)
        for (int t = tid; t < S; t += 256) if (t >= c) buf[t] = ~0ULL;
        __syncthreads();
        for (int k = 2; k <= S; k <<= 1)
            for (int j = k >> 1; j > 0; j >>= 1) {
                for (int t = tid; t < S; t += 256) {
                    int x = t ^ j;
                    if (x > t) {
                        unsigned long long A = buf[t], Bv = buf[x];
                        bool up = ((t & k) == 0);
                        if (up ? (A > Bv) : (A < Bv)) { buf[t] = Bv; buf[x] = A; }
                    }
                }
                __syncthreads();
            }
        if (tid == 0) { cnt = NC; thr_s = buf[NC - 1]; }
        __syncthreads();
    };

    for (int base = 0; base < NPTS; base += 1024) {
#pragma unroll
        for (int i = 0; i < 4; i++) {
            int p = base + tid + i * 256;
            float4 q = pb[p];
            float ab = __fmaf_rn(az, q.z, __fmaf_rn(ay, q.y, __fmul_rn(ax, q.x)));
            float dd = __fsub_rn(__fadd_rn(aa, q.w), __fmul_rn(2.0f, ab));
            unsigned int kb = __float_as_uint(dd);
            kb = (kb & 0x80000000u) ? ~kb : (kb | 0x80000000u);
            unsigned long long key = ((unsigned long long)kb << 32) | (unsigned int)p;
            if (key < thr) {
                int pos = atomicAdd(&cnt, 1);
                if (pos < KCAP) buf[pos] = key;
            }
        }
        __syncthreads();
        if (tid == 0) s_flag = (cnt > 960);
        __syncthreads();
        if (s_flag) { compact(); thr = thr_s; }
    }
    compact();
    if (tid < NC) g_knn[bg * NC + tid] = (int)(unsigned int)(buf[tid] & 0xffffffffu);
}

// ---------------- K5: normalize + s2pf + rescale + resample + assemble ----------------
__global__ void __launch_bounds__(128) k5_patch(const float* __restrict__ sew1, const float* __restrict__ seb1,
                                                const float* __restrict__ sdw1, const float* __restrict__ sdb1,
                                                const float* __restrict__ sdw2, const float* __restrict__ sdb2,
                                                float* __restrict__ out) {
    __shared__ float px[NC], py[NC], pz[NC];
    __shared__ float nx[NC], ny[NC], nz[NC], nrm[NC];
    __shared__ float code[128];
    __shared__ float h2s[NC * 129];
    __shared__ float cen[3];
    __shared__ float ssc;
    __shared__ float pe[NC * 2];
    __shared__ float mnmx[4];
    __shared__ float ebd[NC * 2];
    int bg = blockIdx.x, b = bg >> 8, g = bg & 255, tid = threadIdx.x;

    if (tid < NC) {
        int pi = g_knn[bg * NC + tid];
        float4 q = g_pbb[b * NPTS + pi];
        px[tid] = q.x; py[tid] = q.y; pz[tid] = q.z;
    }
    __syncthreads();
    if (tid < 3) {
        const float* a = (tid == 0) ? px : ((tid == 1) ? py : pz);
        float s = 0.0f;
        for (int i = 0; i < NC; i++) s = __fadd_rn(s, a[i]);
        cen[tid] = __fdiv_rn(s, 64.0f);
    }
    __syncthreads();
    if (tid < NC) {
        float dx = __fsub_rn(px[tid], cen[0]);
        float dy = __fsub_rn(py[tid], cen[1]);
        float dz = __fsub_rn(pz[tid], cen[2]);
        nx[tid] = dx; ny[tid] = dy; nz[tid] = dz;
        nrm[tid] = __fsqrt_rn(__fadd_rn(__fadd_rn(__fmul_rn(dx, dx), __fmul_rn(dy, dy)), __fmul_rn(dz, dz)));
    }
    __syncthreads();
    if (tid == 0) {
        float m = nrm[0];
        for (int i = 1; i < NC; i++) m = fmaxf(m, nrm[i]);
        ssc = __fadd_rn(m, 1e-8f);
    }
    __syncthreads();
    if (tid < NC) {
        nx[tid] = __fdiv_rn(nx[tid], ssc);
        ny[tid] = __fdiv_rn(ny[tid], ssc);
        nz[tid] = __fdiv_rn(nz[tid], ssc);
    }
    __syncthreads();
    {   // s2pf encoder + maxpool
        int j = tid;
        float w0 = sew1[j], w1 = sew1[128 + j], w2 = sew1[256 + j], bb = seb1[j];
        float mx = 0.0f;
        for (int p = 0; p < NC; p++) {
            float a = __fmaf_rn(nz[p], w2, __fmaf_rn(ny[p], w1, __fmul_rn(nx[p], w0)));
            float hh = fmaxf(__fadd_rn(a, bb), 0.0f);
            mx = (p == 0) ? hh : fmaxf(mx, hh);
        }
        code[j] = mx;
    }
    __syncthreads();
    {   // h2 with hoisted code-dot
        int j = tid;
        float base = 0.0f;
        for (int k = 0; k < 128; k++) base = __fmaf_rn(code[k], sdw1[(3 + k) * 128 + j], base);
        float w0 = sdw1[j], w1 = sdw1[128 + j], w2 = sdw1[256 + j], bb = sdb1[j];
        for (int p = 0; p < NC; p++) {
            float a = __fadd_rn(__fmaf_rn(nz[p], w2, __fmaf_rn(ny[p], w1, __fmul_rn(nx[p], w0))), base);
            h2s[p * 129 + j] = fmaxf(__fadd_rn(a, bb), 0.0f);
        }
    }
    __syncthreads();
    {   // pe = h2 @ sd_w2 + b
        int p = tid & 63, c = tid >> 6;
        float s = 0.0f;
        for (int j = 0; j < 128; j++) s = __fmaf_rn(h2s[p * 129 + j], sdw2[j * 2 + c], s);
        pe[p * 2 + c] = __fadd_rn(s, sdb2[c]);
    }
    __syncthreads();
    if (tid < 2) {
        float mn = pe[tid], mx = pe[tid];
        for (int p = 1; p < NC; p++) { float v = pe[p * 2 + tid]; mn = fminf(mn, v); mx = fmaxf(mx, v); }
        mnmx[tid] = mn; mnmx[2 + tid] = mx;
    }
    __syncthreads();
    {
        int p = tid & 63, c = tid >> 6;
        const float HIL = (float)((1.0 - 1e-6) - 1e-6);
        float t = __fdiv_rn(__fsub_rn(pe[p * 2 + c], mnmx[c]),
                            __fadd_rn(__fsub_rn(mnmx[2 + c], mnmx[c]), 1e-8f));
        ebd[p * 2 + c] = __fadd_rn(__fmul_rn(t, HIL), 1e-6f);
    }
    __syncthreads();
    if (tid < 16) {   // per-cell nearest + assemble
        int k = tid;
        float gx = __fmul_rn((float)(k & 3) + 0.5f, 0.25f);
        float gy = __fmul_rn((float)(k >> 2) + 0.5f, 0.25f);
        float bd = 1e30f; int bi = 0;
        for (int p = 0; p < NC; p++) {
            float dx = __fsub_rn(gx, ebd[p * 2]);
            float dy = __fsub_rn(gy, ebd[p * 2 + 1]);
            float d2 = __fadd_rn(__fmul_rn(dx, dx), __fmul_rn(dy, dy));
            if (d2 < bd) { bd = d2; bi = p; }
        }
        int m = ((g >> 4) * 4 + (k >> 2)) * 64 + (g & 15) * 4 + (k & 3);
        float* o = out + ((long)b * 4096 + m) * 3;
        o[0] = px[bi]; o[1] = py[bi]; o[2] = pz[bi];
    }
}

extern "C" void kernel_launch(void* const* d_in, const int* in_sizes, int n_in,
                              void* d_out, int out_size) {
    const float* pts  = (const float*)d_in[0];
    const float* gew1 = (const float*)d_in[1];
    const float* geb1 = (const float*)d_in[2];
    const float* gew2 = (const float*)d_in[3];
    const float* geb2 = (const float*)d_in[4];
    const float* gdw1 = (const float*)d_in[5];
    const float* gdb1 = (const float*)d_in[6];
    const float* gdw2 = (const float*)d_in[7];
    const float* gdb2 = (const float*)d_in[8];
    const float* sew1 = (const float*)d_in[9];
    const float* seb1 = (const float*)d_in[10];
    const float* sdw1 = (const float*)d_in[11];
    const float* sdb1 = (const float*)d_in[12];
    const float* sdw2 = (const float*)d_in[13];
    const float* sdb2 = (const float*)d_in[14];
    float* out = (float*)d_out;

    // probes keep the fixed ncu capture slot (launch #4) on k1_fps
    probe_a<<<1, 32>>>();
    probe_b<<<1, 32>>>();
    k0_prep<<<BATCH * NPTS / 256, 256>>>(pts);
    k1_fps<<<BATCH * 8, 512>>>();
    k2_genc<<<BATCH * NG, 128>>>(gew1, geb1, gew2, geb2);
    k3a<<<BATCH, 256>>>(gdw1);
    k3b<<<BATCH * NG, 256>>>(gdw1, gdb1, gdw2, gdb2);
    k4_knn<<<BATCH * NG, 256>>>();
    k5_patch<<<BATCH * NG, 128>>>(sew1, seb1, sdw1, sdb1, sdw2, sdb2, out);
}

// round 16
// speedup vs baseline: 1.5172x; 1.0427x over previous
#include <cuda_runtime.h>
#include <cstdint>

#define BATCH 8
#define NPTS  32768
#define NG    256
#define NC    64
#define KCAP  2048

__device__ float4 g_pbb[BATCH * NPTS];     // x,y,z,|p|^2 (square-then-add)
__device__ int    g_fps[BATCH * NG];
__device__ float  g_code[BATCH * 256];
__device__ float  g_cdot[BATCH * 256];
__device__ float  g_rec[BATCH * NG * 3];
__device__ int    g_knn[BATCH * NG * NC];

#define PACK2(out, lo, hi) \
    asm("mov.b64 %0, {%1, %2};" : "=l"(out) : "f"(lo), "f"(hi))
#define ADD2(out, a, b) \
    asm("add.rn.f32x2 %0, %1, %2;" : "=l"(out) : "l"(a), "l"(b))
#define MUL2(out, a, b) \
    asm("mul.rn.f32x2 %0, %1, %2;" : "=l"(out) : "l"(a), "l"(b))

// ---------------- probes: keep the fixed ncu capture slot on k1_fps ----------------
__global__ void probe_a() {}
__global__ void probe_b() {}

// ---------------- K0: SoA prep + zero code ----------------
__global__ void k0_prep(const float* __restrict__ pts) {
    int i = blockIdx.x * 256 + threadIdx.x;
    float x = pts[i * 3], y = pts[i * 3 + 1], z = pts[i * 3 + 2];
    float bb = __fadd_rn(__fadd_rn(__fmul_rn(x, x), __fmul_rn(y, y)), __fmul_rn(z, z));
    g_pbb[i] = make_float4(x, y, z, bb);
    if (i < BATCH * 256) g_code[i] = 0.0f;
}

// ---------------- K1: FPS — 8-CTA cluster per batch, f32x2 update ----------------
// R15 structure, two changes:
// (1) winner-xyz extraction moved behind the warp redux (only the per-warp
//     winner lane unpacks px2[bj>>1]) — removes a ~12-instr select chain from
//     every thread's iteration;
// (2) post-barrier exchange scan done by warp 0 only (redux.max on dist bits +
//     redux.min on idx = exact lowest-index tie-break, identical to the old
//     select chain), published via shared + one __syncthreads — removes ~60
//     redundant instr/thread/iter.
// Parity double-buffering unchanged: warp 0 scans parity p before its own
// arrive at barrier it+1, and any remote parity-p overwrite (it+2) is ordered
// after barrier it+1 — race-free.
__global__ void __cluster_dims__(8, 1, 1) __launch_bounds__(512, 1) k1_fps() {
    __shared__ float s_wv[16];
    __shared__ int   s_wi[16];
    __shared__ float s_wx[16], s_wy[16], s_wz[16];
    __shared__ unsigned int s_rec[8];                         // CTA winner record
    __shared__ unsigned int s_fin[4];                         // cluster winner (idx,x,y,z)
    __shared__ __align__(16) unsigned int s_exch[2][8 * 8];   // [parity][cta*8 words]

    int rank = blockIdx.x & 7;
    int b    = blockIdx.x >> 3;
    int tid  = threadIdx.x;
    int base = rank * 4096;

    const float4* __restrict__ pb = g_pbb + b * NPTS;

    // packed point storage: pair m holds points j=2m (lo lane) and j=2m+1 (hi lane)
    unsigned long long px2[4], py2[4], pz2[4];
    unsigned int du[8];
#pragma unroll
    for (int m = 0; m < 4; m++) {
        float4 qa = pb[base + tid + (2 * m) * 512];
        float4 qb = pb[base + tid + (2 * m + 1) * 512];
        PACK2(px2[m], qa.x, qb.x);
        PACK2(py2[m], qa.y, qb.y);
        PACK2(pz2[m], qa.z, qb.z);
        du[2 * m] = du[2 * m + 1] = __float_as_uint(1e10f);
    }
    float4 q0 = pb[0];
    float sx = q0.x, sy = q0.y, sz = q0.z;
    int cur = 0;

    unsigned int ex0 = (unsigned int)__cvta_generic_to_shared(&s_exch[0][0]);
    unsigned int ex1 = (unsigned int)__cvta_generic_to_shared(&s_exch[1][0]);

    for (int it = 0; it < NG; it++) {
        if (rank == 0 && tid == 0) g_fps[b * NG + it] = cur;

        float nsx = -sx, nsy = -sy, nsz = -sz;   // negation is exact
        unsigned long long nsx2, nsy2, nsz2;
        PACK2(nsx2, nsx, nsx);
        PACK2(nsy2, nsy, nsy);
        PACK2(nsz2, nsz, nsz);

        unsigned int bb_ = 0u;
        int bj = 0;
#pragma unroll
        for (int m = 0; m < 4; m++) {
            unsigned long long dx, dy, dz, xx, yy, zz, s;
            ADD2(dx, px2[m], nsx2);
            ADD2(dy, py2[m], nsy2);
            ADD2(dz, pz2[m], nsz2);
            MUL2(xx, dx, dx);
            MUL2(yy, dy, dy);
            MUL2(zz, dz, dz);
            ADD2(s, xx, yy);
            ADD2(s, s, zz);
            unsigned int lo = (unsigned int)s;
            unsigned int hi = (unsigned int)(s >> 32);
            unsigned int n0 = min(du[2 * m], lo);       // uint order == float order (>=0)
            du[2 * m] = n0;
            if (n0 > bb_) { bb_ = n0; bj = 2 * m; }     // strict >: lowest index on ties
            unsigned int n1 = min(du[2 * m + 1], hi);
            du[2 * m + 1] = n1;
            if (n1 > bb_) { bb_ = n1; bj = 2 * m + 1; }
        }
        int bi = base + tid + bj * 512;

        // warp argmax via redux.sync (exact, min-idx ties; idx unique -> one writer)
        unsigned int M  = __reduce_max_sync(0xffffffffu, bb_);
        unsigned int cd = (bb_ == M) ? (unsigned int)bi : 0xffffffffu;
        unsigned int wm = __reduce_min_sync(0xffffffffu, cd);
        if (bb_ == M && (unsigned int)bi == wm) {
            // winner lane only: unpack its xyz
            unsigned long long X = px2[bj >> 1], Y = py2[bj >> 1], Z = pz2[bj >> 1];
            float bx, by, bz;
            if (bj & 1) {
                bx = __uint_as_float((unsigned int)(X >> 32));
                by = __uint_as_float((unsigned int)(Y >> 32));
                bz = __uint_as_float((unsigned int)(Z >> 32));
            } else {
                bx = __uint_as_float((unsigned int)X);
                by = __uint_as_float((unsigned int)Y);
                bz = __uint_as_float((unsigned int)Z);
            }
            int w = tid >> 5;
            s_wv[w] = __uint_as_float(M); s_wi[w] = (int)wm;
            s_wx[w] = bx; s_wy[w] = by; s_wz[w] = bz;
        }
        __syncthreads();

        if (tid < 32) {
            bool ok = tid < 16;
            unsigned int vb = ok ? __float_as_uint(s_wv[tid]) : 0u;
            int          ix = ok ? s_wi[tid] : 0x7fffffff;
            unsigned int M2 = __reduce_max_sync(0xffffffffu, vb);
            unsigned int c2 = (vb == M2) ? (unsigned int)ix : 0xffffffffu;
            unsigned int w2 = __reduce_min_sync(0xffffffffu, c2);
            if (ok && vb == M2 && (unsigned int)ix == w2) {
                s_rec[0] = M2; s_rec[1] = w2;
                s_rec[2] = __float_as_uint(s_wx[tid]);
                s_rec[3] = __float_as_uint(s_wy[tid]);
                s_rec[4] = __float_as_uint(s_wz[tid]);
            }
            __syncwarp();
            if (tid < 8) {
                unsigned int exb = (it & 1) ? ex1 : ex0;
                unsigned int v0 = s_rec[0], v1 = s_rec[1], v2 = s_rec[2],
                             v3 = s_rec[3], v4 = s_rec[4];
                unsigned int ra;
                asm volatile("mapa.shared::cluster.u32 %0, %1, %2;"
                             : "=r"(ra) : "r"(exb + rank * 32), "r"(tid));
                asm volatile("st.shared::cluster.v4.b32 [%0], {%1,%2,%3,%4};"
                             :: "r"(ra), "r"(v0), "r"(v1), "r"(v2), "r"(v3) : "memory");
                asm volatile("st.shared::cluster.b32 [%0+16], %1;"
                             :: "r"(ra), "r"(v4) : "memory");
            }
        }
        asm volatile("barrier.cluster.arrive.aligned;" ::: "memory");
        asm volatile("barrier.cluster.wait.aligned;" ::: "memory");

        // single-warp scan of the 8 records, then publish
        if (tid < 32) {
            const unsigned int* e = s_exch[it & 1];
            unsigned int v = 0u;
            unsigned int ix = 0x7fffffffu;
            unsigned int rx = 0u, ry = 0u, rz = 0u;
            if (tid < 8) {
                v  = e[tid * 8 + 0];
                ix = e[tid * 8 + 1];
                rx = e[tid * 8 + 2];
                ry = e[tid * 8 + 3];
                rz = e[tid * 8 + 4];
            }
            unsigned int M3 = __reduce_max_sync(0xffffffffu, v);
            unsigned int c3 = (v == M3) ? ix : 0xffffffffu;
            unsigned int w3 = __reduce_min_sync(0xffffffffu, c3);
            if (v == M3 && ix == w3 && tid < 8) {   // unique real winner lane
                s_fin[0] = ix; s_fin[1] = rx; s_fin[2] = ry; s_fin[3] = rz;
            }
        }
        __syncthreads();
        cur = (int)s_fin[0];
        sx = __uint_as_float(s_fin[1]);
        sy = __uint_as_float(s_fin[2]);
        sz = __uint_as_float(s_fin[3]);
    }
}

// ---------------- K2: g2sd encoder + maxpool ----------------
__global__ void __launch_bounds__(128) k2_genc(const float* __restrict__ w1, const float* __restrict__ b1,
                                               const float* __restrict__ w2, const float* __restrict__ b2) {
    __shared__ float h1[128];
    int bg = blockIdx.x, b = bg >> 8, j = threadIdx.x;
    int pi = g_fps[bg];
    float4 q = g_pbb[b * NPTS + pi];
    float a = __fmaf_rn(q.z, w1[256 + j], __fmaf_rn(q.y, w1[128 + j], __fmul_rn(q.x, w1[j])));
    h1[j] = fmaxf(__fadd_rn(a, b1[j]), 0.0f);
    __syncthreads();
#pragma unroll
    for (int t = 0; t < 2; t++) {
        int ch = j + t * 128;
        float s = 0.0f;
        for (int k = 0; k < 128; k++) s = __fmaf_rn(h1[k], w2[k * 256 + ch], s);
        float h2 = fmaxf(__fadd_rn(s, b2[ch]), 0.0f);
        atomicMax((int*)&g_code[b * 256 + ch], __float_as_int(h2));
    }
}

// ---------------- K3a: per-batch code @ gd_w1[2:,:] ----------------
__global__ void __launch_bounds__(256) k3a(const float* __restrict__ w1) {
    __shared__ float cs[256];
    int b = blockIdx.x, j = threadIdx.x;
    cs[j] = g_code[b * 256 + j];
    __syncthreads();
    float s = 0.0f;
    for (int k = 0; k < 256; k++) s = __fmaf_rn(cs[k], w1[(2 + k) * 256 + j], s);
    g_cdot[b * 256 + j] = s;
}

// ---------------- K3b: g2sd folding decoder -> rec_g ----------------
__global__ void __launch_bounds__(256) k3b(const float* __restrict__ w1, const float* __restrict__ b1,
                                           const float* __restrict__ w2, const float* __restrict__ b2) {
    __shared__ float h[256];
    int bg = blockIdx.x, b = bg >> 8, g = bg & 255, j = threadIdx.x;
    float gx = __fmul_rn((float)(g & 15) + 0.5f, 0.0625f);
    float gy = __fmul_rn((float)(g >> 4) + 0.5f, 0.0625f);
    float a = __fmaf_rn(gy, w1[256 + j], __fmul_rn(gx, w1[j]));
    a = __fadd_rn(a, g_cdot[b * 256 + j]);
    h[j] = fmaxf(__fadd_rn(a, b1[j]), 0.0f);
    __syncthreads();
    if (j < 3) {
        float s = 0.0f;
        for (int k = 0; k < 256; k++) s = __fmaf_rn(h[k], w2[k * 3 + j], s);
        g_rec[bg * 3 + j] = __fadd_rn(s, b2[j]);
    }
}

// ---------------- K4: exact 64-NN, threshold stream + pow2-sized bitonic compact ----------------
__global__ void __launch_bounds__(256) k4_knn() {
    __shared__ unsigned long long buf[KCAP];
    __shared__ int cnt, s_flag;
    __shared__ unsigned long long thr_s;
    int bg = blockIdx.x, b = bg >> 8, tid = threadIdx.x;
    float ax = g_rec[bg * 3], ay = g_rec[bg * 3 + 1], az = g_rec[bg * 3 + 2];
    float aa = __fadd_rn(__fadd_rn(__fmul_rn(ax, ax), __fmul_rn(ay, ay)), __fmul_rn(az, az));
    if (tid == 0) { cnt = 0; thr_s = ~0ULL; }
    __syncthreads();
    const float4* __restrict__ pb = g_pbb + b * NPTS;
    unsigned long long thr = ~0ULL;

    auto compact = [&]() {
        int c = cnt;                       // uniform (post-sync)
        int S = 64; while (S < c) S <<= 1; // pow2 >= c, >= 64  (c <= 1984 < KCAP)
        for (int t = tid; t < S; t += 256) if (t >= c) buf[t] = ~0ULL;
        __syncthreads();
        for (int k = 2; k <= S; k <<= 1)
            for (int j = k >> 1; j > 0; j >>= 1) {
                for (int t = tid; t < S; t += 256) {
                    int x = t ^ j;
                    if (x > t) {
                        unsigned long long A = buf[t], Bv = buf[x];
                        bool up = ((t & k) == 0);
                        if (up ? (A > Bv) : (A < Bv)) { buf[t] = Bv; buf[x] = A; }
                    }
                }
                __syncthreads();
            }
        if (tid == 0) { cnt = NC; thr_s = buf[NC - 1]; }
        __syncthreads();
    };

    for (int base = 0; base < NPTS; base += 1024) {
#pragma unroll
        for (int i = 0; i < 4; i++) {
            int p = base + tid + i * 256;
            float4 q = pb[p];
            float ab = __fmaf_rn(az, q.z, __fmaf_rn(ay, q.y, __fmul_rn(ax, q.x)));
            float dd = __fsub_rn(__fadd_rn(aa, q.w), __fmul_rn(2.0f, ab));
            unsigned int kb = __float_as_uint(dd);
            kb = (kb & 0x80000000u) ? ~kb : (kb | 0x80000000u);
            unsigned long long key = ((unsigned long long)kb << 32) | (unsigned int)p;
            if (key < thr) {
                int pos = atomicAdd(&cnt, 1);
                if (pos < KCAP) buf[pos] = key;
            }
        }
        __syncthreads();
        if (tid == 0) s_flag = (cnt > 960);
        __syncthreads();
        if (s_flag) { compact(); thr = thr_s; }
    }
    compact();
    if (tid < NC) g_knn[bg * NC + tid] = (int)(unsigned int)(buf[tid] & 0xffffffffu);
}

// ---------------- K5: normalize + s2pf + rescale + resample + assemble ----------------
__global__ void __launch_bounds__(128) k5_patch(const float* __restrict__ sew1, const float* __restrict__ seb1,
                                                const float* __restrict__ sdw1, const float* __restrict__ sdb1,
                                                const float* __restrict__ sdw2, const float* __restrict__ sdb2,
                                                float* __restrict__ out) {
    __shared__ float px[NC], py[NC], pz[NC];
    __shared__ float nx[NC], ny[NC], nz[NC], nrm[NC];
    __shared__ float code[128];
    __shared__ float h2s[NC * 129];
    __shared__ float cen[3];
    __shared__ float ssc;
    __shared__ float pe[NC * 2];
    __shared__ float mnmx[4];
    __shared__ float ebd[NC * 2];
    int bg = blockIdx.x, b = bg >> 8, g = bg & 255, tid = threadIdx.x;

    if (tid < NC) {
        int pi = g_knn[bg * NC + tid];
        float4 q = g_pbb[b * NPTS + pi];
        px[tid] = q.x; py[tid] = q.y; pz[tid] = q.z;
    }
    __syncthreads();
    if (tid < 3) {
        const float* a = (tid == 0) ? px : ((tid == 1) ? py : pz);
        float s = 0.0f;
        for (int i = 0; i < NC; i++) s = __fadd_rn(s, a[i]);
        cen[tid] = __fdiv_rn(s, 64.0f);
    }
    __syncthreads();
    if (tid < NC) {
        float dx = __fsub_rn(px[tid], cen[0]);
        float dy = __fsub_rn(py[tid], cen[1]);
        float dz = __fsub_rn(pz[tid], cen[2]);
        nx[tid] = dx; ny[tid] = dy; nz[tid] = dz;
        nrm[tid] = __fsqrt_rn(__fadd_rn(__fadd_rn(__fmul_rn(dx, dx), __fmul_rn(dy, dy)), __fmul_rn(dz, dz)));
    }
    __syncthreads();
    if (tid == 0) {
        float m = nrm[0];
        for (int i = 1; i < NC; i++) m = fmaxf(m, nrm[i]);
        ssc = __fadd_rn(m, 1e-8f);
    }
    __syncthreads();
    if (tid < NC) {
        nx[tid] = __fdiv_rn(nx[tid], ssc);
        ny[tid] = __fdiv_rn(ny[tid], ssc);
        nz[tid] = __fdiv_rn(nz[tid], ssc);
    }
    __syncthreads();
    {   // s2pf encoder + maxpool
        int j = tid;
        float w0 = sew1[j], w1 = sew1[128 + j], w2 = sew1[256 + j], bb = seb1[j];
        float mx = 0.0f;
        for (int p = 0; p < NC; p++) {
            float a = __fmaf_rn(nz[p], w2, __fmaf_rn(ny[p], w1, __fmul_rn(nx[p], w0)));
            float hh = fmaxf(__fadd_rn(a, bb), 0.0f);
            mx = (p == 0) ? hh : fmaxf(mx, hh);
        }
        code[j] = mx;
    }
    __syncthreads();
    {   // h2 with hoisted code-dot
        int j = tid;
        float base = 0.0f;
        for (int k = 0; k < 128; k++) base = __fmaf_rn(code[k], sdw1[(3 + k) * 128 + j], base);
        float w0 = sdw1[j], w1 = sdw1[128 + j], w2 = sdw1[256 + j], bb = sdb1[j];
        for (int p = 0; p < NC; p++) {
            float a = __fadd_rn(__fmaf_rn(nz[p], w2, __fmaf_rn(ny[p], w1, __fmul_rn(nx[p], w0))), base);
            h2s[p * 129 + j] = fmaxf(__fadd_rn(a, bb), 0.0f);
        }
    }
    __syncthreads();
    {   // pe = h2 @ sd_w2 + b
        int p = tid & 63, c = tid >> 6;
        float s = 0.0f;
        for (int j = 0; j < 128; j++) s = __fmaf_rn(h2s[p * 129 + j], sdw2[j * 2 + c], s);
        pe[p * 2 + c] = __fadd_rn(s, sdb2[c]);
    }
    __syncthreads();
    if (tid < 2) {
        float mn = pe[tid], mx = pe[tid];
        for (int p = 1; p < NC; p++) { float v = pe[p * 2 + tid]; mn = fminf(mn, v); mx = fmaxf(mx, v); }
        mnmx[tid] = mn; mnmx[2 + tid] = mx;
    }
    __syncthreads();
    {
        int p = tid & 63, c = tid >> 6;
        const float HIL = (float)((1.0 - 1e-6) - 1e-6);
        float t = __fdiv_rn(__fsub_rn(pe[p * 2 + c], mnmx[c]),
                            __fadd_rn(__fsub_rn(mnmx[2 + c], mnmx[c]), 1e-8f));
        ebd[p * 2 + c] = __fadd_rn(__fmul_rn(t, HIL), 1e-6f);
    }
    __syncthreads();
    if (tid < 16) {   // per-cell nearest + assemble
        int k = tid;
        float gx = __fmul_rn((float)(k & 3) + 0.5f, 0.25f);
        float gy = __fmul_rn((float)(k >> 2) + 0.5f, 0.25f);
        float bd = 1e30f; int bi = 0;
        for (int p = 0; p < NC; p++) {
            float dx = __fsub_rn(gx, ebd[p * 2]);
            float dy = __fsub_rn(gy, ebd[p * 2 + 1]);
            float d2 = __fadd_rn(__fmul_rn(dx, dx), __fmul_rn(dy, dy));
            if (d2 < bd) { bd = d2; bi = p; }
        }
        int m = ((g >> 4) * 4 + (k >> 2)) * 64 + (g & 15) * 4 + (k & 3);
        float* o = out + ((long)b * 4096 + m) * 3;
        o[0] = px[bi]; o[1] = py[bi]; o[2] = pz[bi];
    }
}

extern "C" void kernel_launch(void* const* d_in, const int* in_sizes, int n_in,
                              void* d_out, int out_size) {
    const float* pts  = (const float*)d_in[0];
    const float* gew1 = (const float*)d_in[1];
    const float* geb1 = (const float*)d_in[2];
    const float* gew2 = (const float*)d_in[3];
    const float* geb2 = (const float*)d_in[4];
    const float* gdw1 = (const float*)d_in[5];
    const float* gdb1 = (const float*)d_in[6];
    const float* gdw2 = (const float*)d_in[7];
    const float* gdb2 = (const float*)d_in[8];
    const float* sew1 = (const float*)d_in[9];
    const float* seb1 = (const float*)d_in[10];
    const float* sdw1 = (const float*)d_in[11];
    const float* sdb1 = (const float*)d_in[12];
    const float* sdw2 = (const float*)d_in[13];
    const float* sdb2 = (const float*)d_in[14];
    float* out = (float*)d_out;

    // probes keep the fixed ncu capture slot (launch #4) on k1_fps
    probe_a<<<1, 32>>>();
    probe_b<<<1, 32>>>();
    k0_prep<<<BATCH * NPTS / 256, 256>>>(pts);
    k1_fps<<<BATCH * 8, 512>>>();
    k2_genc<<<BATCH * NG, 128>>>(gew1, geb1, gew2, geb2);
    k3a<<<BATCH, 256>>>(gdw1);
    k3b<<<BATCH * NG, 256>>>(gdw1, gdb1, gdw2, gdb2);
    k4_knn<<<BATCH * NG, 256>>>();
    k5_patch<<<BATCH * NG, 128>>>(sew1, seb1, sdw1, sdb1, sdw2, sdb2, out);
}

// round 17
// speedup vs baseline: 2.2428x; 1.4783x over previous
#include <cuda_runtime.h>
#include <cstdint>

#define BATCH 8
#define NPTS  32768
#define NG    256
#define NC    64
#define KCAP  2048

__device__ float4 g_pbb[BATCH * NPTS];     // x,y,z,|p|^2 (square-then-add)
__device__ int    g_fps[BATCH * NG];
__device__ float  g_code[BATCH * 256];
__device__ float  g_cdot[BATCH * 256];
__device__ float  g_rec[BATCH * NG * 3];
__device__ int    g_knn[BATCH * NG * NC];

#define PACK2(out, lo, hi) \
    asm("mov.b64 %0, {%1, %2};" : "=l"(out) : "f"(lo), "f"(hi))
#define ADD2(out, a, b) \
    asm("add.rn.f32x2 %0, %1, %2;" : "=l"(out) : "l"(a), "l"(b))
#define MUL2(out, a, b) \
    asm("mul.rn.f32x2 %0, %1, %2;" : "=l"(out) : "l"(a), "l"(b))

// ---------------- probe: put the fixed ncu capture slot (#4) on k2_genc ----------------
__global__ void probe_a() {}

// ---------------- K0: SoA prep + zero code ----------------
__global__ void k0_prep(const float* __restrict__ pts) {
    int i = blockIdx.x * 256 + threadIdx.x;
    float x = pts[i * 3], y = pts[i * 3 + 1], z = pts[i * 3 + 2];
    float bb = __fadd_rn(__fadd_rn(__fmul_rn(x, x), __fmul_rn(y, y)), __fmul_rn(z, z));
    g_pbb[i] = make_float4(x, y, z, bb);
    if (i < BATCH * 256) g_code[i] = 0.0f;
}

// ---------------- K1: FPS — 8-CTA cluster per batch (R16, unchanged) ----------------
__global__ void __cluster_dims__(8, 1, 1) __launch_bounds__(512, 1) k1_fps() {
    __shared__ float s_wv[16];
    __shared__ int   s_wi[16];
    __shared__ float s_wx[16], s_wy[16], s_wz[16];
    __shared__ unsigned int s_rec[8];                         // CTA winner record
    __shared__ unsigned int s_fin[4];                         // cluster winner (idx,x,y,z)
    __shared__ __align__(16) unsigned int s_exch[2][8 * 8];   // [parity][cta*8 words]

    int rank = blockIdx.x & 7;
    int b    = blockIdx.x >> 3;
    int tid  = threadIdx.x;
    int base = rank * 4096;

    const float4* __restrict__ pb = g_pbb + b * NPTS;

    unsigned long long px2[4], py2[4], pz2[4];
    unsigned int du[8];
#pragma unroll
    for (int m = 0; m < 4; m++) {
        float4 qa = pb[base + tid + (2 * m) * 512];
        float4 qb = pb[base + tid + (2 * m + 1) * 512];
        PACK2(px2[m], qa.x, qb.x);
        PACK2(py2[m], qa.y, qb.y);
        PACK2(pz2[m], qa.z, qb.z);
        du[2 * m] = du[2 * m + 1] = __float_as_uint(1e10f);
    }
    float4 q0 = pb[0];
    float sx = q0.x, sy = q0.y, sz = q0.z;
    int cur = 0;

    unsigned int ex0 = (unsigned int)__cvta_generic_to_shared(&s_exch[0][0]);
    unsigned int ex1 = (unsigned int)__cvta_generic_to_shared(&s_exch[1][0]);

    for (int it = 0; it < NG; it++) {
        if (rank == 0 && tid == 0) g_fps[b * NG + it] = cur;

        float nsx = -sx, nsy = -sy, nsz = -sz;
        unsigned long long nsx2, nsy2, nsz2;
        PACK2(nsx2, nsx, nsx);
        PACK2(nsy2, nsy, nsy);
        PACK2(nsz2, nsz, nsz);

        unsigned int bb_ = 0u;
        int bj = 0;
#pragma unroll
        for (int m = 0; m < 4; m++) {
            unsigned long long dx, dy, dz, xx, yy, zz, s;
            ADD2(dx, px2[m], nsx2);
            ADD2(dy, py2[m], nsy2);
            ADD2(dz, pz2[m], nsz2);
            MUL2(xx, dx, dx);
            MUL2(yy, dy, dy);
            MUL2(zz, dz, dz);
            ADD2(s, xx, yy);
            ADD2(s, s, zz);
            unsigned int lo = (unsigned int)s;
            unsigned int hi = (unsigned int)(s >> 32);
            unsigned int n0 = min(du[2 * m], lo);
            du[2 * m] = n0;
            if (n0 > bb_) { bb_ = n0; bj = 2 * m; }
            unsigned int n1 = min(du[2 * m + 1], hi);
            du[2 * m + 1] = n1;
            if (n1 > bb_) { bb_ = n1; bj = 2 * m + 1; }
        }
        int bi = base + tid + bj * 512;

        unsigned int M  = __reduce_max_sync(0xffffffffu, bb_);
        unsigned int cd = (bb_ == M) ? (unsigned int)bi : 0xffffffffu;
        unsigned int wm = __reduce_min_sync(0xffffffffu, cd);
        if (bb_ == M && (unsigned int)bi == wm) {
            unsigned long long X = px2[bj >> 1], Y = py2[bj >> 1], Z = pz2[bj >> 1];
            float bx, by, bz;
            if (bj & 1) {
                bx = __uint_as_float((unsigned int)(X >> 32));
                by = __uint_as_float((unsigned int)(Y >> 32));
                bz = __uint_as_float((unsigned int)(Z >> 32));
            } else {
                bx = __uint_as_float((unsigned int)X);
                by = __uint_as_float((unsigned int)Y);
                bz = __uint_as_float((unsigned int)Z);
            }
            int w = tid >> 5;
            s_wv[w] = __uint_as_float(M); s_wi[w] = (int)wm;
            s_wx[w] = bx; s_wy[w] = by; s_wz[w] = bz;
        }
        __syncthreads();

        if (tid < 32) {
            bool ok = tid < 16;
            unsigned int vb = ok ? __float_as_uint(s_wv[tid]) : 0u;
            int          ix = ok ? s_wi[tid] : 0x7fffffff;
            unsigned int M2 = __reduce_max_sync(0xffffffffu, vb);
            unsigned int c2 = (vb == M2) ? (unsigned int)ix : 0xffffffffu;
            unsigned int w2 = __reduce_min_sync(0xffffffffu, c2);
            if (ok && vb == M2 && (unsigned int)ix == w2) {
                s_rec[0] = M2; s_rec[1] = w2;
                s_rec[2] = __float_as_uint(s_wx[tid]);
                s_rec[3] = __float_as_uint(s_wy[tid]);
                s_rec[4] = __float_as_uint(s_wz[tid]);
            }
            __syncwarp();
            if (tid < 8) {
                unsigned int exb = (it & 1) ? ex1 : ex0;
                unsigned int v0 = s_rec[0], v1 = s_rec[1], v2 = s_rec[2],
                             v3 = s_rec[3], v4 = s_rec[4];
                unsigned int ra;
                asm volatile("mapa.shared::cluster.u32 %0, %1, %2;"
                             : "=r"(ra) : "r"(exb + rank * 32), "r"(tid));
                asm volatile("st.shared::cluster.v4.b32 [%0], {%1,%2,%3,%4};"
                             :: "r"(ra), "r"(v0), "r"(v1), "r"(v2), "r"(v3) : "memory");
                asm volatile("st.shared::cluster.b32 [%0+16], %1;"
                             :: "r"(ra), "r"(v4) : "memory");
            }
        }
        asm volatile("barrier.cluster.arrive.aligned;" ::: "memory");
        asm volatile("barrier.cluster.wait.aligned;" ::: "memory");

        if (tid < 32) {
            const unsigned int* e = s_exch[it & 1];
            unsigned int v = 0u;
            unsigned int ix = 0x7fffffffu;
            unsigned int rx = 0u, ry = 0u, rz = 0u;
            if (tid < 8) {
                v  = e[tid * 8 + 0];
                ix = e[tid * 8 + 1];
                rx = e[tid * 8 + 2];
                ry = e[tid * 8 + 3];
                rz = e[tid * 8 + 4];
            }
            unsigned int M3 = __reduce_max_sync(0xffffffffu, v);
            unsigned int c3 = (v == M3) ? ix : 0xffffffffu;
            unsigned int w3 = __reduce_min_sync(0xffffffffu, c3);
            if (v == M3 && ix == w3 && tid < 8) {
                s_fin[0] = ix; s_fin[1] = rx; s_fin[2] = ry; s_fin[3] = rz;
            }
        }
        __syncthreads();
        cur = (int)s_fin[0];
        sx = __uint_as_float(s_fin[1]);
        sy = __uint_as_float(s_fin[2]);
        sz = __uint_as_float(s_fin[3]);
    }
}

// ---------------- K2: g2sd encoder + maxpool ----------------
__global__ void __launch_bounds__(128) k2_genc(const float* __restrict__ w1, const float* __restrict__ b1,
                                               const float* __restrict__ w2, const float* __restrict__ b2) {
    __shared__ float h1[128];
    int bg = blockIdx.x, b = bg >> 8, j = threadIdx.x;
    int pi = g_fps[bg];
    float4 q = g_pbb[b * NPTS + pi];
    float a = __fmaf_rn(q.z, w1[256 + j], __fmaf_rn(q.y, w1[128 + j], __fmul_rn(q.x, w1[j])));
    h1[j] = fmaxf(__fadd_rn(a, b1[j]), 0.0f);
    __syncthreads();
#pragma unroll
    for (int t = 0; t < 2; t++) {
        int ch = j + t * 128;
        float s = 0.0f;
        for (int k = 0; k < 128; k++) s = __fmaf_rn(h1[k], w2[k * 256 + ch], s);
        float h2 = fmaxf(__fadd_rn(s, b2[ch]), 0.0f);
        atomicMax((int*)&g_code[b * 256 + ch], __float_as_int(h2));
    }
}

// ---------------- K3a: per-batch code @ gd_w1[2:,:] ----------------
__global__ void __launch_bounds__(256) k3a(const float* __restrict__ w1) {
    __shared__ float cs[256];
    int b = blockIdx.x, j = threadIdx.x;
    cs[j] = g_code[b * 256 + j];
    __syncthreads();
    float s = 0.0f;
    for (int k = 0; k < 256; k++) s = __fmaf_rn(cs[k], w1[(2 + k) * 256 + j], s);
    g_cdot[b * 256 + j] = s;
}

// ---------------- K3b: g2sd folding decoder -> rec_g ----------------
__global__ void __launch_bounds__(256) k3b(const float* __restrict__ w1, const float* __restrict__ b1,
                                           const float* __restrict__ w2, const float* __restrict__ b2) {
    __shared__ float h[256];
    int bg = blockIdx.x, b = bg >> 8, g = bg & 255, j = threadIdx.x;
    float gx = __fmul_rn((float)(g & 15) + 0.5f, 0.0625f);
    float gy = __fmul_rn((float)(g >> 4) + 0.5f, 0.0625f);
    float a = __fmaf_rn(gy, w1[256 + j], __fmul_rn(gx, w1[j]));
    a = __fadd_rn(a, g_cdot[b * 256 + j]);
    h[j] = fmaxf(__fadd_rn(a, b1[j]), 0.0f);
    __syncthreads();
    if (j < 3) {
        float s = 0.0f;
        for (int k = 0; k < 256; k++) s = __fmaf_rn(h[k], w2[k * 3 + j], s);
        g_rec[bg * 3 + j] = __fadd_rn(s, b2[j]);
    }
}

// ---------------- K4: exact 64-NN — threshold stream, histogram-select compact ----------------
// Intermediate compactions: 256-bin histogram on key bits [63:56] + warp scan
// to find the bin B where cumulative >= 64, then register-staged in-place
// partition keeping digit <= B, thr = (B+1)<<56. EXACT-SUPERSET of the true
// top-64 (K64's digit <= B since cum(B) >= 64), so the final exact bitonic
// sort yields identical output. Fallback to the exact bitonic compact when the
// partition leaves cnt > 960 (degenerate exponent clustering). Capacity:
// post-compact cnt <= 960 (either path), chunk adds <= 1024 => cnt <= 1984 < KCAP.
__global__ void __launch_bounds__(256) k4_knn() {
    __shared__ unsigned long long buf[KCAP];
    __shared__ int cnt, s_flag, s_bin;
    __shared__ int hist[256];
    __shared__ unsigned long long thr_s;
    int bg = blockIdx.x, b = bg >> 8, tid = threadIdx.x;
    float ax = g_rec[bg * 3], ay = g_rec[bg * 3 + 1], az = g_rec[bg * 3 + 2];
    float aa = __fadd_rn(__fadd_rn(__fmul_rn(ax, ax), __fmul_rn(ay, ay)), __fmul_rn(az, az));
    if (tid == 0) { cnt = 0; thr_s = ~0ULL; }
    __syncthreads();
    const float4* __restrict__ pb = g_pbb + b * NPTS;
    unsigned long long thr = ~0ULL;

    // exact bitonic compact: sorts ascending by (d, idx), sets cnt=64, exact thr
    auto compact = [&]() {
        int c = cnt;                       // uniform (post-sync)
        int S = 64; while (S < c) S <<= 1; // pow2 >= c (c <= 1984 < KCAP)
        for (int t = tid; t < S; t += 256) if (t >= c) buf[t] = ~0ULL;
        __syncthreads();
        for (int k = 2; k <= S; k <<= 1)
            for (int j = k >> 1; j > 0; j >>= 1) {
                for (int t = tid; t < S; t += 256) {
                    int x = t ^ j;
                    if (x > t) {
                        unsigned long long A = buf[t], Bv = buf[x];
                        bool up = ((t & k) == 0);
                        if (up ? (A > Bv) : (A < Bv)) { buf[t] = Bv; buf[x] = A; }
                    }
                }
                __syncthreads();
            }
        if (tid == 0) { cnt = NC; thr_s = buf[NC - 1]; }
        __syncthreads();
    };

    // histogram-select partition (exact superset, loose threshold)
    auto hcompact = [&]() {
        int c = cnt;                       // uniform (post-sync), 960 < c <= 1984
        hist[tid] = 0;                     // 256 threads == 256 bins
        __syncthreads();
        unsigned long long it_[8];
        int nit = 0;
        for (int t = tid; t < c; t += 256) it_[nit++] = buf[t];
#pragma unroll 4
        for (int k = 0; k < nit; k++)
            atomicAdd(&hist[(int)(unsigned int)(it_[k] >> 56)], 1);
        __syncthreads();
        if (tid < 32) {   // warp-parallel scan: lane l owns bins [8l, 8l+8)
            int part[8], s = 0;
#pragma unroll
            for (int i = 0; i < 8; i++) { part[i] = hist[tid * 8 + i]; s += part[i]; }
            int run = s;
#pragma unroll
            for (int off = 1; off < 32; off <<= 1) {
                int v = __shfl_up_sync(0xffffffffu, run, off);
                if (tid >= off) run += v;
            }
            int excl = run - s;
            bool has = (excl < NC) && (run >= NC);
            unsigned int msk = __ballot_sync(0xffffffffu, has);
            int lane = __ffs(msk) - 1;
            if (tid == lane) {
                int cum = excl, B = tid * 8 + 7;
#pragma unroll
                for (int i = 0; i < 8; i++) { cum += part[i]; if (cum >= NC) { B = tid * 8 + i; break; } }
                s_bin = B;
                cnt = 0;
            }
        }
        __syncthreads();
        int B = s_bin;
        for (int k = 0; k < nit; k++) {
            if ((int)(unsigned int)(it_[k] >> 56) <= B) {
                int pos = atomicAdd(&cnt, 1);
                buf[pos] = it_[k];
            }
        }
        __syncthreads();
        if (tid == 0) thr_s = ((unsigned long long)(unsigned int)(B + 1)) << 56;
        __syncthreads();
    };

    for (int base = 0; base < NPTS; base += 1024) {
#pragma unroll
        for (int i = 0; i < 4; i++) {
            int p = base + tid + i * 256;
            float4 q = pb[p];
            float ab = __fmaf_rn(az, q.z, __fmaf_rn(ay, q.y, __fmul_rn(ax, q.x)));
            float dd = __fsub_rn(__fadd_rn(aa, q.w), __fmul_rn(2.0f, ab));
            unsigned int kb = __float_as_uint(dd);
            kb = (kb & 0x80000000u) ? ~kb : (kb | 0x80000000u);
            unsigned long long key = ((unsigned long long)kb << 32) | (unsigned int)p;
            if (key < thr) {
                int pos = atomicAdd(&cnt, 1);
                if (pos < KCAP) buf[pos] = key;   // never fires (cnt <= 1984)
            }
        }
        __syncthreads();
        if (tid == 0) s_flag = (cnt > 960);
        __syncthreads();
        if (s_flag) {
            hcompact();
            if (cnt > 960) compact();   // uniform (post-sync) fallback, exact
            thr = thr_s;
        }
    }
    compact();   // final exact sort: buf[0..63] ascending by (d, idx)
    if (tid < NC) g_knn[bg * NC + tid] = (int)(unsigned int)(buf[tid] & 0xffffffffu);
}

// ---------------- K5: normalize + s2pf + rescale + resample + assemble ----------------
__global__ void __launch_bounds__(128) k5_patch(const float* __restrict__ sew1, const float* __restrict__ seb1,
                                                const float* __restrict__ sdw1, const float* __restrict__ sdb1,
                                                const float* __restrict__ sdw2, const float* __restrict__ sdb2,
                                                float* __restrict__ out) {
    __shared__ float px[NC], py[NC], pz[NC];
    __shared__ float nx[NC], ny[NC], nz[NC], nrm[NC];
    __shared__ float code[128];
    __shared__ float h2s[NC * 129];
    __shared__ float cen[3];
    __shared__ float ssc;
    __shared__ float pe[NC * 2];
    __shared__ float mnmx[4];
    __shared__ float ebd[NC * 2];
    int bg = blockIdx.x, b = bg >> 8, g = bg & 255, tid = threadIdx.x;

    if (tid < NC) {
        int pi = g_knn[bg * NC + tid];
        float4 q = g_pbb[b * NPTS + pi];
        px[tid] = q.x; py[tid] = q.y; pz[tid] = q.z;
    }
    __syncthreads();
    if (tid < 3) {
        const float* a = (tid == 0) ? px : ((tid == 1) ? py : pz);
        float s = 0.0f;
        for (int i = 0; i < NC; i++) s = __fadd_rn(s, a[i]);
        cen[tid] = __fdiv_rn(s, 64.0f);
    }
    __syncthreads();
    if (tid < NC) {
        float dx = __fsub_rn(px[tid], cen[0]);
        float dy = __fsub_rn(py[tid], cen[1]);
        float dz = __fsub_rn(pz[tid], cen[2]);
        nx[tid] = dx; ny[tid] = dy; nz[tid] = dz;
        nrm[tid] = __fsqrt_rn(__fadd_rn(__fadd_rn(__fmul_rn(dx, dx), __fmul_rn(dy, dy)), __fmul_rn(dz, dz)));
    }
    __syncthreads();
    if (tid == 0) {
        float m = nrm[0];
        for (int i = 1; i < NC; i++) m = fmaxf(m, nrm[i]);
        ssc = __fadd_rn(m, 1e-8f);
    }
    __syncthreads();
    if (tid < NC) {
        nx[tid] = __fdiv_rn(nx[tid], ssc);
        ny[tid] = __fdiv_rn(ny[tid], ssc);
        nz[tid] = __fdiv_rn(nz[tid], ssc);
    }
    __syncthreads();
    {   // s2pf encoder + maxpool
        int j = tid;
        float w0 = sew1[j], w1 = sew1[128 + j], w2 = sew1[256 + j], bb = seb1[j];
        float mx = 0.0f;
        for (int p = 0; p < NC; p++) {
            float a = __fmaf_rn(nz[p], w2, __fmaf_rn(ny[p], w1, __fmul_rn(nx[p], w0)));
            float hh = fmaxf(__fadd_rn(a, bb), 0.0f);
            mx = (p == 0) ? hh : fmaxf(mx, hh);
        }
        code[j] = mx;
    }
    __syncthreads();
    {   // h2 with hoisted code-dot
        int j = tid;
        float base = 0.0f;
        for (int k = 0; k < 128; k++) base = __fmaf_rn(code[k], sdw1[(3 + k) * 128 + j], base);
        float w0 = sdw1[j], w1 = sdw1[128 + j], w2 = sdw1[256 + j], bb = sdb1[j];
        for (int p = 0; p < NC; p++) {
            float a = __fadd_rn(__fmaf_rn(nz[p], w2, __fmaf_rn(ny[p], w1, __fmul_rn(nx[p], w0))), base);
            h2s[p * 129 + j] = fmaxf(__fadd_rn(a, bb), 0.0f);
        }
    }
    __syncthreads();
    {   // pe = h2 @ sd_w2 + b
        int p = tid & 63, c = tid >> 6;
        float s = 0.0f;
        for (int j = 0; j < 128; j++) s = __fmaf_rn(h2s[p * 129 + j], sdw2[j * 2 + c], s);
        pe[p * 2 + c] = __fadd_rn(s, sdb2[c]);
    }
    __syncthreads();
    if (tid < 2) {
        float mn = pe[tid], mx = pe[tid];
        for (int p = 1; p < NC; p++) { float v = pe[p * 2 + tid]; mn = fminf(mn, v); mx = fmaxf(mx, v); }
        mnmx[tid] = mn; mnmx[2 + tid] = mx;
    }
    __syncthreads();
    {
        int p = tid & 63, c = tid >> 6;
        const float HIL = (float)((1.0 - 1e-6) - 1e-6);
        float t = __fdiv_rn(__fsub_rn(pe[p * 2 + c], mnmx[c]),
                            __fadd_rn(__fsub_rn(mnmx[2 + c], mnmx[c]), 1e-8f));
        ebd[p * 2 + c] = __fadd_rn(__fmul_rn(t, HIL), 1e-6f);
    }
    __syncthreads();
    if (tid < 16) {   // per-cell nearest + assemble
        int k = tid;
        float gx = __fmul_rn((float)(k & 3) + 0.5f, 0.25f);
        float gy = __fmul_rn((float)(k >> 2) + 0.5f, 0.25f);
        float bd = 1e30f; int bi = 0;
        for (int p = 0; p < NC; p++) {
            float dx = __fsub_rn(gx, ebd[p * 2]);
            float dy = __fsub_rn(gy, ebd[p * 2 + 1]);
            float d2 = __fadd_rn(__fmul_rn(dx, dx), __fmul_rn(dy, dy));
            if (d2 < bd) { bd = d2; bi = p; }
        }
        int m = ((g >> 4) * 4 + (k >> 2)) * 64 + (g & 15) * 4 + (k & 3);
        float* o = out + ((long)b * 4096 + m) * 3;
        o[0] = px[bi]; o[1] = py[bi]; o[2] = pz[bi];
    }
}

extern "C" void kernel_launch(void* const* d_in, const int* in_sizes, int n_in,
                              void* d_out, int out_size) {
    const float* pts  = (const float*)d_in[0];
    const float* gew1 = (const float*)d_in[1];
    const float* geb1 = (const float*)d_in[2];
    const float* gew2 = (const float*)d_in[3];
    const float* geb2 = (const float*)d_in[4];
    const float* gdw1 = (const float*)d_in[5];
    const float* gdb1 = (const float*)d_in[6];
    const float* gdw2 = (const float*)d_in[7];
    const float* gdb2 = (const float*)d_in[8];
    const float* sew1 = (const float*)d_in[9];
    const float* seb1 = (const float*)d_in[10];
    const float* sdw1 = (const float*)d_in[11];
    const float* sdb1 = (const float*)d_in[12];
    const float* sdw2 = (const float*)d_in[13];
    const float* sdb2 = (const float*)d_in[14];
    float* out = (float*)d_out;

    // 1 probe: the fixed ncu capture slot (launch #4) lands on k2_genc
    probe_a<<<1, 32>>>();
    k0_prep<<<BATCH * NPTS / 256, 256>>>(pts);
    k1_fps<<<BATCH * 8, 512>>>();
    k2_genc<<<BATCH * NG, 128>>>(gew1, geb1, gew2, geb2);
    k3a<<<BATCH, 256>>>(gdw1);
    k3b<<<BATCH * NG, 256>>>(gdw1, gdb1, gdw2, gdb2);
    k4_knn<<<BATCH * NG, 256>>>();
    k5_patch<<<BATCH * NG, 128>>>(sew1, seb1, sdw1, sdb1, sdw2, sdb2, out);
}